// round 14
// baseline (speedup 1.0000x reference)
#include <cuda_runtime.h>
#include <math.h>
#include <stdint.h>

// ---------------- problem constants ----------------
#define NB   4
#define NT   1024
#define NC   768
#define NH   12
#define NHD  64
#define NL   12
#define NV   50257
#define NBT  (NB*NT)     // 4096
#define NBTV (NBT*NV)

// weight plane offsets (uint32 units, transposed [N][K/2] per matrix)
#define OFF_QKV  0LL
#define SZ_QKV   (2304LL*384)
#define OFF_PROJ (OFF_QKV + 12*SZ_QKV)
#define SZ_PROJ  (768LL*384)
#define OFF_FC   (OFF_PROJ + 12*SZ_PROJ)
#define SZ_FC    (3072LL*384)
#define OFF_FC2  (OFF_FC + 12*SZ_FC)
#define SZ_FC2   (768LL*1536)
#define OFF_HEAD (OFF_FC2 + 12*SZ_FC2)
#define SZ_HEAD  (50257LL*384)
#define W_TOTAL  (OFF_HEAD + SZ_HEAD)

// ---------------- scratch ----------------
__device__ float    g_x   [NBT*NC];
__device__ float    g_qkv [NBT*3*NC];
__device__ uint32_t g_h_hi [NBT*NC/2];
__device__ uint32_t g_h_lo [NBT*NC/2];
__device__ uint32_t g_att_hi[NBT*NC/2];
__device__ uint32_t g_att_lo[NBT*NC/2];
__device__ uint32_t g_fch_hi[NBT*4*NC/2];
__device__ uint32_t g_fch_lo[NBT*4*NC/2];
__device__ uint32_t g_whi[W_TOTAL];
__device__ uint32_t g_wlo[W_TOTAL];
// packed attention operand planes: Q/K rows [bh][t][32w], Vt [bh][d][512w]
#define QK_WORDS (NB*NH*NT*32)
__device__ uint32_t g_qphi[QK_WORDS];
__device__ uint32_t g_qplo[QK_WORDS];
__device__ uint32_t g_kphi[QK_WORDS];
__device__ uint32_t g_kplo[QK_WORDS];
__device__ uint32_t g_vthi[QK_WORDS];
__device__ uint32_t g_vtlo[QK_WORDS];
__device__ float    g_logits_scratch[NBTV];
__device__ float    g_loss_sum;
__device__ float    g_loss_cnt;

__device__ __forceinline__ float gelu_f(float u) {
    return 0.5f * u * (1.0f + tanhf(0.7978845608028654f * (u + 0.044715f * u * u * u)));
}

__device__ __forceinline__ uint32_t pack_bf2(float even, float odd) {
    uint32_t r;
    asm("cvt.rn.bf16x2.f32 %0, %1, %2;" : "=r"(r) : "f"(odd), "f"(even));
    return r;
}
__device__ __forceinline__ uint32_t lo_pair(uint32_t hp, float even, float odd) {
    float e_h = __uint_as_float(hp << 16);
    float o_h = __uint_as_float(hp & 0xffff0000u);
    return pack_bf2(even - e_h, odd - o_h);
}

__device__ __forceinline__ void mma_bf16(float* c, const uint32_t* a, const uint32_t* b) {
    asm volatile(
        "mma.sync.aligned.m16n8k16.row.col.f32.bf16.bf16.f32 "
        "{%0,%1,%2,%3}, {%4,%5,%6,%7}, {%8,%9}, {%0,%1,%2,%3};"
        : "+f"(c[0]), "+f"(c[1]), "+f"(c[2]), "+f"(c[3])
        : "r"(a[0]), "r"(a[1]), "r"(a[2]), "r"(a[3]), "r"(b[0]), "r"(b[1]));
}

__device__ __forceinline__ uint32_t smem_u32(const void* p) {
    uint32_t a;
    asm("{ .reg .u64 t; cvta.to.shared.u64 t, %1; cvt.u32.u64 %0, t; }" : "=r"(a) : "l"(p));
    return a;
}
__device__ __forceinline__ void cpa16(uint32_t saddr, const void* g, uint32_t srcsz) {
    asm volatile("cp.async.cg.shared.global [%0], [%1], 16, %2;"
                 :: "r"(saddr), "l"(g), "r"(srcsz) : "memory");
}
#define CPA_COMMIT() asm volatile("cp.async.commit_group;" ::: "memory")
#define CPA_WAIT4()  asm volatile("cp.async.wait_group 4;" ::: "memory")
#define CPA_WAIT1()  asm volatile("cp.async.wait_group 1;" ::: "memory")
#define CPA_WAIT0()  asm volatile("cp.async.wait_group 0;" ::: "memory")

__device__ __forceinline__ void ldsm4(uint32_t* r, uint32_t addr) {
    asm volatile("ldmatrix.sync.aligned.m8n8.x4.shared.b16 {%0,%1,%2,%3}, [%4];"
                 : "=r"(r[0]), "=r"(r[1]), "=r"(r[2]), "=r"(r[3]) : "r"(addr));
}

// ---------------- small kernels ----------------
__global__ void k_zero_loss(float* s, float* c) { *s = 0.f; *c = 0.f; }

__global__ void k_embed(const int* __restrict__ idx,
                        const float* __restrict__ wte,
                        const float* __restrict__ wpe,
                        float* __restrict__ x)
{
    int i = blockIdx.x * blockDim.x + threadIdx.x;
    if (i >= NBT * NC) return;
    int c  = i % NC;
    int bt = i / NC;
    int t  = bt % NT;
    x[i] = wte[(long long)idx[bt] * NC + c] + wpe[t * NC + c];
}

// ---- single-launch weight transpose+split over all 49 matrices ----
#define WS_TOTAL_BLOCKS 60324
__global__ void k_wsplit_all(const float* __restrict__ qkv_w,
                             const float* __restrict__ proj_w,
                             const float* __restrict__ fc_w,
                             const float* __restrict__ fc2_w,
                             const float* __restrict__ head_w,
                             uint32_t* __restrict__ Whi,
                             uint32_t* __restrict__ Wlo)
{
    __shared__ uint32_t shi[32][33];
    __shared__ uint32_t slo[32][33];

    int bid = blockIdx.x;
    const float* W;
    long long dst;
    int K, N, ntn, t;
    if (bid < 10368) {
        int m = bid / 864; t = bid % 864;
        W = qkv_w + (long long)m * 768 * 2304; dst = OFF_QKV + m * SZ_QKV;
        K = 768; N = 2304; ntn = 72;
    } else if (bid < 13824) {
        bid -= 10368; int m = bid / 288; t = bid % 288;
        W = proj_w + (long long)m * 768 * 768; dst = OFF_PROJ + m * SZ_PROJ;
        K = 768; N = 768; ntn = 24;
    } else if (bid < 27648) {
        bid -= 13824; int m = bid / 1152; t = bid % 1152;
        W = fc_w + (long long)m * 768 * 3072; dst = OFF_FC + m * SZ_FC;
        K = 768; N = 3072; ntn = 96;
    } else if (bid < 41472) {
        bid -= 27648; int m = bid / 1152; t = bid % 1152;
        W = fc2_w + (long long)m * 3072 * 768; dst = OFF_FC2 + m * SZ_FC2;
        K = 3072; N = 768; ntn = 24;
    } else {
        t = bid - 41472;
        W = head_w; dst = OFF_HEAD;
        K = 768; N = NV; ntn = 1571;
    }
    const int K2 = K >> 1;
    const int n0  = (t % ntn) * 32;
    const int kp0 = (t / ntn) * 32;
    const int tx = threadIdx.x;
    const int ty = threadIdx.y;

    #pragma unroll
    for (int r = ty; r < 32; r += 8) {
        int kp = kp0 + r;
        int n  = n0 + tx;
        if (kp < K2 && n < N) {
            float w0 = W[(long long)(2 * kp) * N + n];
            float w1 = W[(long long)(2 * kp + 1) * N + n];
            uint32_t hp = pack_bf2(w0, w1);
            shi[r][tx] = hp;
            slo[r][tx] = lo_pair(hp, w0, w1);
        }
    }
    __syncthreads();
    #pragma unroll
    for (int r = ty; r < 32; r += 8) {
        int n  = n0 + r;
        int kp = kp0 + tx;
        if (kp < K2 && n < N) {
            long long o = dst + (long long)n * K2 + kp;
            Whi[o] = shi[tx][r];
            Wlo[o] = slo[tx][r];
        }
    }
}

// ---- warp-per-row layernorm -> packed planes ----
__global__ __launch_bounds__(128)
void k_layernorm_p(const float* __restrict__ x,
                   const float* __restrict__ w,
                   const float* __restrict__ b,
                   uint32_t* __restrict__ hhi,
                   uint32_t* __restrict__ hlo)
{
    const int lane = threadIdx.x & 31;
    const int row = blockIdx.x * 4 + (threadIdx.x >> 5);
    const float* xr = x + (long long)row * NC;

    float4 v[6];
    #pragma unroll
    for (int j = 0; j < 6; j++)
        v[j] = *(const float4*)(xr + (j * 32 + lane) * 4);

    float s = 0.f;
    #pragma unroll
    for (int j = 0; j < 6; j++) s += v[j].x + v[j].y + v[j].z + v[j].w;
    #pragma unroll
    for (int off = 16; off > 0; off >>= 1) s += __shfl_xor_sync(0xffffffffu, s, off);
    const float mu = s * (1.0f / NC);

    float var = 0.f;
    #pragma unroll
    for (int j = 0; j < 6; j++) {
        float a0 = v[j].x - mu, a1 = v[j].y - mu, a2 = v[j].z - mu, a3 = v[j].w - mu;
        var += a0 * a0 + a1 * a1 + a2 * a2 + a3 * a3;
    }
    #pragma unroll
    for (int off = 16; off > 0; off >>= 1) var += __shfl_xor_sync(0xffffffffu, var, off);
    const float rstd = rsqrtf(var * (1.0f / NC) + 1e-5f);

    const long long base = (long long)row * (NC / 2);
    #pragma unroll
    for (int j = 0; j < 6; j++) {
        const int c = (j * 32 + lane) * 4;
        float n0 = (v[j].x - mu) * rstd * w[c]     + b[c];
        float n1 = (v[j].y - mu) * rstd * w[c + 1] + b[c + 1];
        float n2 = (v[j].z - mu) * rstd * w[c + 2] + b[c + 2];
        float n3 = (v[j].w - mu) * rstd * w[c + 3] + b[c + 3];
        uint2 hp, lp;
        hp.x = pack_bf2(n0, n1); lp.x = lo_pair(hp.x, n0, n1);
        hp.y = pack_bf2(n2, n3); lp.y = lo_pair(hp.y, n2, n3);
        *(uint2*)(hhi + base + (c >> 1)) = hp;
        *(uint2*)(hlo + base + (c >> 1)) = lp;
    }
}

// ---- per-layer QKV -> packed attention planes (convert once) ----
__global__ __launch_bounds__(128)
void k_qkvsplit(const float* __restrict__ qkv,
                uint32_t* __restrict__ qhi, uint32_t* __restrict__ qlo,
                uint32_t* __restrict__ khi, uint32_t* __restrict__ klo,
                uint32_t* __restrict__ vthi, uint32_t* __restrict__ vtlo)
{
    __shared__ float stage[64][68];
    const int t0 = blockIdx.x * 64;
    const int h  = blockIdx.y;
    const int b  = blockIdx.z;
    const int tid = threadIdx.x;
    const int r = tid >> 1;
    const int hc = tid & 1;
    const long long bh = (long long)(b * NH + h);
    const float* base = qkv + (long long)b * NT * 3 * NC;

    {
        const float* qrow = base + (long long)(t0 + r) * (3 * NC) + h * NHD + hc * 32;
        const float* krow = qrow + NC;
        const long long out = (bh * NT + t0 + r) * 32 + hc * 16;
        #pragma unroll
        for (int c4 = 0; c4 < 4; c4++) {
            uint4 qh, ql, kh, kl;
            uint32_t* qhp = &qh.x; uint32_t* qlp = &ql.x;
            uint32_t* khp = &kh.x; uint32_t* klp = &kl.x;
            #pragma unroll
            for (int e = 0; e < 4; e++) {
                const int wd = c4 * 4 + e;
                float qe = qrow[2 * wd], qo = qrow[2 * wd + 1];
                qhp[e] = pack_bf2(qe, qo); qlp[e] = lo_pair(qhp[e], qe, qo);
                float ke = krow[2 * wd], ko = krow[2 * wd + 1];
                khp[e] = pack_bf2(ke, ko); klp[e] = lo_pair(khp[e], ke, ko);
            }
            *(uint4*)(qhi + out + c4 * 4) = qh;
            *(uint4*)(qlo + out + c4 * 4) = ql;
            *(uint4*)(khi + out + c4 * 4) = kh;
            *(uint4*)(klo + out + c4 * 4) = kl;
        }
    }

    {
        const float* vrow = base + (long long)(t0 + r) * (3 * NC) + 2 * NC + h * NHD + hc * 32;
        #pragma unroll
        for (int j = 0; j < 8; j++)
            *(float4*)(&stage[r][hc * 32 + j * 4]) = *(const float4*)(vrow + j * 4);
    }
    __syncthreads();

    {
        const int d = r;
        const long long out = (bh * NHD + d) * (NT / 2) + t0 / 2 + hc * 16;
        #pragma unroll
        for (int c4 = 0; c4 < 4; c4++) {
            uint4 vh, vl;
            uint32_t* vhp = &vh.x; uint32_t* vlp = &vl.x;
            #pragma unroll
            for (int e = 0; e < 4; e++) {
                const int tok = hc * 32 + (c4 * 4 + e) * 2;
                float ve = stage[tok][d], vo = stage[tok + 1][d];
                vhp[e] = pack_bf2(ve, vo); vlp[e] = lo_pair(vhp[e], ve, vo);
            }
            *(uint4*)(vthi + out + c4 * 4) = vh;
            *(uint4*)(vtlo + out + c4 * 4) = vl;
        }
    }
}

// ---------------- split-bf16 GEMM, 128x128 tile (proj/fc2) ----------------
#define GEMM_SMEM 98304

__global__ __launch_bounds__(256, 2)
void k_gemm_bf(const uint32_t* __restrict__ Ahi, const uint32_t* __restrict__ Alo,
               const uint32_t* __restrict__ Bhi, const uint32_t* __restrict__ Blo,
               const float* __restrict__ bias, const float* __restrict__ res,
               float* __restrict__ Cf,
               uint32_t* __restrict__ Chi, uint32_t* __restrict__ Clo,
               int M, int N, int K2, int act)
{
    extern __shared__ uint32_t smw[];
    const uint32_t sbase = smem_u32(smw);

    const int tid  = threadIdx.x;
    const int lane = tid & 31;
    const int w    = tid >> 5;
    const int bm   = blockIdx.x * 128;
    const int bn   = blockIdx.y * 128;
    const int wm   = (w & 1) * 64;
    const int wn   = (w >> 1) * 32;
    const int g    = lane >> 2;
    const int tig  = lane & 3;

    const int m    = tid >> 1;
    const int half = tid & 1;
    const uint32_t swoff = (uint32_t)((half ^ ((m >> 2) & 1)) << 4);
    const long long aoff = (long long)(bm + m) * K2 + half * 4;
    const int bn_row = (bn + m < N) ? (bn + m) : (N - 1);
    const long long boff = (long long)bn_row * K2 + half * 4;
    const uint32_t bsz = (bn + m < N) ? 16u : 0u;

    const int l15 = lane & 15;
    const uint32_t a_sw = (uint32_t)((((lane >> 4) << 2) ^ (((l15 >> 2) & 1) << 2)) << 2);
    const uint32_t a_base = sbase + (uint32_t)(wm + l15) * 32 + a_sw;
    const int l8 = lane & 7;
    const uint32_t b_sw = (uint32_t)(((((lane >> 3) & 1) << 2) ^ (((l8 >> 2) & 1) << 2)) << 2);
    const uint32_t b_base = sbase + 8192u +
        (uint32_t)(wn + ((lane >> 4) & 1) * 8 + l8) * 32 + b_sw;

    float acc[16][4];
    #pragma unroll
    for (int i = 0; i < 16; i++)
        #pragma unroll
        for (int j = 0; j < 4; j++) acc[i][j] = 0.f;

#define ISSUE_STAGE(S_) do {                                              \
        const int _buf = (S_) % 6;                                        \
        const uint32_t _so = sbase + _buf * 16384 + m * 32 + swoff;       \
        const long long _ko = (long long)(S_) * 8;                        \
        cpa16(_so,         Ahi + aoff + _ko, 16u);                        \
        cpa16(_so + 4096,  Alo + aoff + _ko, 16u);                        \
        cpa16(_so + 8192,  Bhi + boff + _ko, bsz);                        \
        cpa16(_so + 12288, Blo + boff + _ko, bsz);                        \
        CPA_COMMIT();                                                     \
    } while (0)

    const int S = K2 >> 3;
    ISSUE_STAGE(0);
    ISSUE_STAGE(1);
    ISSUE_STAGE(2);
    ISSUE_STAGE(3);
    ISSUE_STAGE(4);

    for (int s = 0; s < S; s++) {
        CPA_WAIT4();
        __syncthreads();
        if (s + 5 < S) { ISSUE_STAGE(s + 5); } else { CPA_COMMIT(); }

        const uint32_t stoff = (uint32_t)((s % 6) * 16384);

        uint32_t bh[8], bl[8];
        ldsm4(bh,     b_base + stoff);
        ldsm4(bh + 4, b_base + stoff + 512);
        ldsm4(bl,     b_base + stoff + 4096);
        ldsm4(bl + 4, b_base + stoff + 4096 + 512);

        #pragma unroll
        for (int mt = 0; mt < 4; mt++) {
            uint32_t ah[4], al[4];
            ldsm4(ah, a_base + stoff + mt * 512);
            ldsm4(al, a_base + stoff + mt * 512 + 4096);
            #pragma unroll
            for (int nt = 0; nt < 4; nt++) {
                mma_bf16(acc[mt * 4 + nt], ah, bh + nt * 2);
                mma_bf16(acc[mt * 4 + nt], ah, bl + nt * 2);
                mma_bf16(acc[mt * 4 + nt], al, bh + nt * 2);
            }
        }
    }
#undef ISSUE_STAGE

    const bool evenN = ((N & 1) == 0);
    #pragma unroll
    for (int mt = 0; mt < 4; mt++) {
        #pragma unroll
        for (int nt = 0; nt < 4; nt++) {
            const float* c = acc[mt * 4 + nt];
            const int n = bn + wn + nt * 8 + tig * 2;
            #pragma unroll
            for (int hf = 0; hf < 2; hf++) {
                const int mm = bm + wm + mt * 16 + g + hf * 8;
                float v0 = c[hf * 2 + 0];
                float v1 = c[hf * 2 + 1];
                if (act == 1) {
                    if (bias) { v0 += bias[n]; v1 += bias[n + 1]; }
                    v0 = gelu_f(v0); v1 = gelu_f(v1);
                    uint32_t hp = pack_bf2(v0, v1);
                    long long o = (long long)mm * (N >> 1) + (n >> 1);
                    Chi[o] = hp;
                    Clo[o] = lo_pair(hp, v0, v1);
                } else {
                    const long long rowoff = (long long)mm * N;
                    if (n + 1 < N) {
                        if (bias) { v0 += bias[n]; v1 += bias[n + 1]; }
                        if (res)  { v0 += res[rowoff + n]; v1 += res[rowoff + n + 1]; }
                        if (evenN) {
                            *(float2*)(Cf + rowoff + n) = make_float2(v0, v1);
                        } else {
                            Cf[rowoff + n]     = v0;
                            Cf[rowoff + n + 1] = v1;
                        }
                    } else if (n < N) {
                        if (bias) v0 += bias[n];
                        if (res)  v0 += res[rowoff + n];
                        Cf[rowoff + n] = v0;
                    }
                }
            }
        }
    }
}

// ---------------- split-bf16 GEMM, 256x128 tile (qkv/fc/head) -------------
// 8 warps (4m x 2n), warp tile 64x64. 1 CTA/SM. Stage = 24KB (Ahi 8K | Alo 8K |
// Bhi 4K | Blo 4K), 6 stages = 144KB. Same swizzle/pipeline as k_gemm_bf.
#define GEMM2_SMEM 147456

__global__ __launch_bounds__(256, 1)
void k_gemm_bf2(const uint32_t* __restrict__ Ahi, const uint32_t* __restrict__ Alo,
                const uint32_t* __restrict__ Bhi, const uint32_t* __restrict__ Blo,
                const float* __restrict__ bias, const float* __restrict__ res,
                float* __restrict__ Cf,
                uint32_t* __restrict__ Chi, uint32_t* __restrict__ Clo,
                int M, int N, int K2, int act)
{
    extern __shared__ uint32_t smw[];
    const uint32_t sbase = smem_u32(smw);

    const int tid  = threadIdx.x;
    const int lane = tid & 31;
    const int w    = tid >> 5;
    const int bm   = blockIdx.x * 256;
    const int bn   = blockIdx.y * 128;
    const int wm   = (w & 3) * 64;
    const int wn   = (w >> 2) * 64;
    const int g    = lane >> 2;
    const int tig  = lane & 3;

    const int am   = tid >> 1;          // 0..127
    const int half = tid & 1;
    const uint32_t swoff = (uint32_t)((half ^ ((am >> 2) & 1)) << 4);
    const long long aoff0 = (long long)(bm + am) * K2 + half * 4;
    const long long aoff1 = (long long)(bm + am + 128) * K2 + half * 4;
    const int bn_row = (bn + am < N) ? (bn + am) : (N - 1);
    const long long boff = (long long)bn_row * K2 + half * 4;
    const uint32_t bsz = (bn + am < N) ? 16u : 0u;

    const int l15 = lane & 15;
    const uint32_t a_sw = (uint32_t)((((lane >> 4) << 2) ^ (((l15 >> 2) & 1) << 2)) << 2);
    const uint32_t a_base = sbase + (uint32_t)(wm + l15) * 32 + a_sw;
    const int l8 = lane & 7;
    const uint32_t b_sw = (uint32_t)(((((lane >> 3) & 1) << 2) ^ (((l8 >> 2) & 1) << 2)) << 2);
    const uint32_t b_base = sbase + 16384u +
        (uint32_t)(wn + ((lane >> 4) & 1) * 8 + l8) * 32 + b_sw;

    float acc[32][4];
    #pragma unroll
    for (int i = 0; i < 32; i++)
        #pragma unroll
        for (int j = 0; j < 4; j++) acc[i][j] = 0.f;

#define ISSUE_STAGE2(S_) do {                                              \
        const int _buf = (S_) % 6;                                         \
        const uint32_t _so = sbase + _buf * 24576 + am * 32 + swoff;       \
        const long long _ko = (long long)(S_) * 8;                         \
        cpa16(_so,                Ahi + aoff0 + _ko, 16u);                 \
        cpa16(_so + 4096,         Ahi + aoff1 + _ko, 16u);                 \
        cpa16(_so + 8192,         Alo + aoff0 + _ko, 16u);                 \
        cpa16(_so + 8192 + 4096,  Alo + aoff1 + _ko, 16u);                 \
        cpa16(_so + 16384,        Bhi + boff + _ko, bsz);                  \
        cpa16(_so + 20480,        Blo + boff + _ko, bsz);                  \
        CPA_COMMIT();                                                      \
    } while (0)

    const int S = K2 >> 3;
    ISSUE_STAGE2(0);
    ISSUE_STAGE2(1);
    ISSUE_STAGE2(2);
    ISSUE_STAGE2(3);
    ISSUE_STAGE2(4);

    for (int s = 0; s < S; s++) {
        CPA_WAIT4();
        __syncthreads();
        if (s + 5 < S) { ISSUE_STAGE2(s + 5); } else { CPA_COMMIT(); }

        const uint32_t stoff = (uint32_t)((s % 6) * 24576);

        uint32_t bh[16], bl[16];
        #pragma unroll
        for (int q = 0; q < 4; q++) {
            ldsm4(bh + q * 4, b_base + stoff + q * 512);
            ldsm4(bl + q * 4, b_base + stoff + 4096 + q * 512);
        }

        #pragma unroll
        for (int mt = 0; mt < 4; mt++) {
            uint32_t ah[4], al[4];
            ldsm4(ah, a_base + stoff + mt * 512);
            ldsm4(al, a_base + stoff + mt * 512 + 8192);
            #pragma unroll
            for (int nt = 0; nt < 8; nt++) {
                mma_bf16(acc[mt * 8 + nt], ah, bh + nt * 2);
                mma_bf16(acc[mt * 8 + nt], ah, bl + nt * 2);
                mma_bf16(acc[mt * 8 + nt], al, bh + nt * 2);
            }
        }
    }
#undef ISSUE_STAGE2

    const bool evenN = ((N & 1) == 0);
    #pragma unroll
    for (int mt = 0; mt < 4; mt++) {
        #pragma unroll
        for (int nt = 0; nt < 8; nt++) {
            const float* c = acc[mt * 8 + nt];
            const int n = bn + wn + nt * 8 + tig * 2;
            #pragma unroll
            for (int hf = 0; hf < 2; hf++) {
                const int mm = bm + wm + mt * 16 + g + hf * 8;
                float v0 = c[hf * 2 + 0];
                float v1 = c[hf * 2 + 1];
                if (act == 1) {
                    if (bias) { v0 += bias[n]; v1 += bias[n + 1]; }
                    v0 = gelu_f(v0); v1 = gelu_f(v1);
                    uint32_t hp = pack_bf2(v0, v1);
                    long long o = (long long)mm * (N >> 1) + (n >> 1);
                    Chi[o] = hp;
                    Clo[o] = lo_pair(hp, v0, v1);
                } else {
                    const long long rowoff = (long long)mm * N;
                    if (n + 1 < N) {
                        if (bias) { v0 += bias[n]; v1 += bias[n + 1]; }
                        if (res)  { v0 += res[rowoff + n]; v1 += res[rowoff + n + 1]; }
                        if (evenN) {
                            *(float2*)(Cf + rowoff + n) = make_float2(v0, v1);
                        } else {
                            Cf[rowoff + n]     = v0;
                            Cf[rowoff + n + 1] = v1;
                        }
                    } else if (n < N) {
                        if (bias) v0 += bias[n];
                        if (res)  v0 += res[rowoff + n];
                        Cf[rowoff + n] = v0;
                    }
                }
            }
        }
    }
}

// ---------------- tensor-core flash attention (precomputed planes) --------
#define ATT_SMEM 81920

__global__ __launch_bounds__(128)
void k_attn_mma(const uint32_t* __restrict__ qphi, const uint32_t* __restrict__ qplo,
                const uint32_t* __restrict__ kphi, const uint32_t* __restrict__ kplo,
                const uint32_t* __restrict__ vthi, const uint32_t* __restrict__ vtlo,
                uint32_t* __restrict__ yhi, uint32_t* __restrict__ ylo)
{
    extern __shared__ char smatt[];
    const uint32_t sb = smem_u32(smatt);

    const int tid  = threadIdx.x;
    const int lane = tid & 31;
    const int w    = tid >> 5;
    const int g    = lane >> 2;
    const int tig  = lane & 3;
    const int q0   = blockIdx.x * 64;
    const int h    = blockIdx.y;
    const int b    = blockIdx.z;
    const long long bh = (long long)(b * NH + h);

    const int r  = tid >> 1;
    const int cb = (tid & 1) * 4;
    const uint32_t rsw = (uint32_t)(r & 7);

    {
        const long long grow = (bh * NT + q0 + r) * 32;
        const uint32_t so = sb + (uint32_t)(r * 128);
        #pragma unroll
        for (int cc = 0; cc < 4; cc++) {
            const int c = cb + cc;
            const uint32_t sw = (uint32_t)((c ^ rsw) << 4);
            cpa16(so + sw,        qphi + grow + c * 4, 16u);
            cpa16(so + 8192 + sw, qplo + grow + c * 4, 16u);
        }
        CPA_COMMIT();
    }

#define ISSUE_KV(J_) do {                                                   \
        const uint32_t _bo = sb + 16384u + (uint32_t)(((J_) & 1) * 32768);  \
        const long long _kg = (bh * NT + (long long)(J_) * 64 + r) * 32;    \
        const long long _vg = (bh * NHD + r) * (NT / 2) + (long long)(J_) * 32; \
        const uint32_t _so = _bo + (uint32_t)(r * 128);                     \
        _Pragma("unroll")                                                   \
        for (int cc = 0; cc < 4; cc++) {                                    \
            const int c = cb + cc;                                          \
            const uint32_t sw = (uint32_t)((c ^ rsw) << 4);                 \
            cpa16(_so + sw,         kphi + _kg + c * 4, 16u);               \
            cpa16(_so + 8192 + sw,  kplo + _kg + c * 4, 16u);               \
            cpa16(_so + 16384 + sw, vthi + _vg + c * 4, 16u);               \
            cpa16(_so + 24576 + sw, vtlo + _vg + c * 4, 16u);               \
        }                                                                   \
        CPA_COMMIT();                                                       \
    } while (0)

    const int ntiles = blockIdx.x + 1;
    ISSUE_KV(0);

    float oC[8][4];
    #pragma unroll
    for (int i = 0; i < 8; i++)
        #pragma unroll
        for (int j = 0; j < 4; j++) oC[i][j] = 0.f;
    float mi0 = -1e30f, mi1 = -1e30f, li0 = 0.f, li1 = 0.f;

    const int qw = w * 16;
    const int r0 = q0 + qw + g;
    const int r1 = r0 + 8;

    for (int tj = 0; tj < ntiles; tj++) {
        const int j0 = tj * 64;
        if (tj + 1 < ntiles) { ISSUE_KV(tj + 1); CPA_WAIT1(); }
        else                 { CPA_WAIT0(); }
        __syncthreads();

        const uint32_t kb = sb + 16384u + (uint32_t)((tj & 1) * 32768);

        float sC[8][4];
        #pragma unroll
        for (int i = 0; i < 8; i++)
            #pragma unroll
            for (int j = 0; j < 4; j++) sC[i][j] = 0.f;

        #pragma unroll
        for (int ks = 0; ks < 4; ks++) {
            const int ar = qw + (lane & 15);
            const uint32_t aaddr = sb + (uint32_t)(ar * 128 +
                (((2 * ks + (lane >> 4)) ^ (ar & 7)) << 4));
            uint32_t qa_h[4], qa_l[4];
            ldsm4(qa_h, aaddr);
            ldsm4(qa_l, aaddr + 8192);
            #pragma unroll
            for (int np = 0; np < 4; np++) {
                const int br = np * 16 + ((lane >> 4) & 1) * 8 + (lane & 7);
                const uint32_t baddr = kb + (uint32_t)(br * 128 +
                    (((2 * ks + ((lane >> 3) & 1)) ^ (br & 7)) << 4));
                uint32_t kb_h[4], kb_l[4];
                ldsm4(kb_h, baddr);
                ldsm4(kb_l, baddr + 8192);
                mma_bf16(sC[2*np],   qa_h, kb_h);
                mma_bf16(sC[2*np],   qa_h, kb_l);
                mma_bf16(sC[2*np],   qa_l, kb_h);
                mma_bf16(sC[2*np+1], qa_h, kb_h + 2);
                mma_bf16(sC[2*np+1], qa_h, kb_l + 2);
                mma_bf16(sC[2*np+1], qa_l, kb_h + 2);
            }
        }

        const bool diag = (tj + 1 == ntiles);
        #pragma unroll
        for (int nt = 0; nt < 8; nt++) {
            const int c0 = j0 + nt * 8 + tig * 2;
            if (diag) {
                sC[nt][0] = (c0     <= r0) ? sC[nt][0] * 0.125f : -1e30f;
                sC[nt][1] = (c0 + 1 <= r0) ? sC[nt][1] * 0.125f : -1e30f;
                sC[nt][2] = (c0     <= r1) ? sC[nt][2] * 0.125f : -1e30f;
                sC[nt][3] = (c0 + 1 <= r1) ? sC[nt][3] * 0.125f : -1e30f;
            } else {
                sC[nt][0] *= 0.125f; sC[nt][1] *= 0.125f;
                sC[nt][2] *= 0.125f; sC[nt][3] *= 0.125f;
            }
        }

        float m0 = -1e30f, m1 = -1e30f;
        #pragma unroll
        for (int nt = 0; nt < 8; nt++) {
            m0 = fmaxf(m0, fmaxf(sC[nt][0], sC[nt][1]));
            m1 = fmaxf(m1, fmaxf(sC[nt][2], sC[nt][3]));
        }
        m0 = fmaxf(m0, __shfl_xor_sync(0xffffffffu, m0, 1));
        m0 = fmaxf(m0, __shfl_xor_sync(0xffffffffu, m0, 2));
        m1 = fmaxf(m1, __shfl_xor_sync(0xffffffffu, m1, 1));
        m1 = fmaxf(m1, __shfl_xor_sync(0xffffffffu, m1, 2));
        const float mn0 = fmaxf(mi0, m0), mn1 = fmaxf(mi1, m1);
        const float corr0 = __expf(mi0 - mn0), corr1 = __expf(mi1 - mn1);

        float rs0 = 0.f, rs1 = 0.f;
        uint32_t pa_h[4][4], pa_l[4][4];
        #pragma unroll
        for (int nt = 0; nt < 8; nt++) {
            float p0 = __expf(sC[nt][0] - mn0);
            float p1 = __expf(sC[nt][1] - mn0);
            float p2 = __expf(sC[nt][2] - mn1);
            float p3 = __expf(sC[nt][3] - mn1);
            rs0 += p0 + p1; rs1 += p2 + p3;
            const int ks = nt >> 1;
            const int rb = (nt & 1) * 2;
            uint32_t u01 = pack_bf2(p0, p1);
            uint32_t u23 = pack_bf2(p2, p3);
            pa_h[ks][rb]     = u01; pa_l[ks][rb]     = lo_pair(u01, p0, p1);
            pa_h[ks][rb + 1] = u23; pa_l[ks][rb + 1] = lo_pair(u23, p2, p3);
        }
        rs0 += __shfl_xor_sync(0xffffffffu, rs0, 1);
        rs0 += __shfl_xor_sync(0xffffffffu, rs0, 2);
        rs1 += __shfl_xor_sync(0xffffffffu, rs1, 1);
        rs1 += __shfl_xor_sync(0xffffffffu, rs1, 2);
        li0 = li0 * corr0 + rs0; mi0 = mn0;
        li1 = li1 * corr1 + rs1; mi1 = mn1;
        #pragma unroll
        for (int nt = 0; nt < 8; nt++) {
            oC[nt][0] *= corr0; oC[nt][1] *= corr0;
            oC[nt][2] *= corr1; oC[nt][3] *= corr1;
        }

        #pragma unroll
        for (int ks = 0; ks < 4; ks++) {
            #pragma unroll
            for (int np = 0; np < 4; np++) {
                const int br = np * 16 + ((lane >> 4) & 1) * 8 + (lane & 7);
                const uint32_t baddr = kb + 16384u + (uint32_t)(br * 128 +
                    (((2 * ks + ((lane >> 3) & 1)) ^ (br & 7)) << 4));
                uint32_t vb_h[4], vb_l[4];
                ldsm4(vb_h, baddr);
                ldsm4(vb_l, baddr + 8192);
                mma_bf16(oC[2*np],   pa_h[ks], vb_h);
                mma_bf16(oC[2*np],   pa_h[ks], vb_l);
                mma_bf16(oC[2*np],   pa_l[ks], vb_h);
                mma_bf16(oC[2*np+1], pa_h[ks], vb_h + 2);
                mma_bf16(oC[2*np+1], pa_h[ks], vb_l + 2);
                mma_bf16(oC[2*np+1], pa_l[ks], vb_h + 2);
            }
        }
        __syncthreads();
    }
#undef ISSUE_KV

    const float inv0 = 1.0f / li0, inv1 = 1.0f / li1;
    #pragma unroll
    for (int nt = 0; nt < 8; nt++) {
        const long long o0 = (long long)(b * NT + r0) * (NC / 2) + h * (NHD / 2) + nt * 4 + tig;
        const long long o1 = (long long)(b * NT + r1) * (NC / 2) + h * (NHD / 2) + nt * 4 + tig;
        float a0 = oC[nt][0] * inv0, a1 = oC[nt][1] * inv0;
        float a2 = oC[nt][2] * inv1, a3 = oC[nt][3] * inv1;
        uint32_t h0 = pack_bf2(a0, a1);
        uint32_t h1 = pack_bf2(a2, a3);
        yhi[o0] = h0; ylo[o0] = lo_pair(h0, a0, a1);
        yhi[o1] = h1; ylo[o1] = lo_pair(h1, a2, a3);
    }
}

// ---------------- loss (one-pass online softmax) ----------------
__global__ void k_loss_rows(const float* __restrict__ logits,
                            const int* __restrict__ targets,
                            float* loss_sum, float* loss_cnt)
{
    int row = blockIdx.x;
    int tid = threadIdx.x;
    const float* lr = logits + (long long)row * NV;
    __shared__ float rm[256];
    __shared__ float rs[256];

    float m = -1e30f, ssum = 0.f;
    for (int i = tid; i < NV; i += 256) {
        float xv = lr[i];
        if (xv > m) { ssum = ssum * __expf(m - xv) + 1.f; m = xv; }
        else        { ssum += __expf(xv - m); }
    }
    rm[tid] = m; rs[tid] = ssum; __syncthreads();
    for (int o = 128; o > 0; o >>= 1) {
        if (tid < o) {
            float m2 = rm[tid + o], s2 = rs[tid + o];
            float mn = fmaxf(rm[tid], m2);
            rs[tid] = rs[tid] * __expf(rm[tid] - mn) + s2 * __expf(m2 - mn);
            rm[tid] = mn;
        }
        __syncthreads();
    }

    if (tid == 0) {
        int t = targets[row];
        if (t != -1) {
            int tc = t < 0 ? 0 : (t > NV - 1 ? NV - 1 : t);
            float nll = (rm[0] + logf(rs[0])) - lr[tc];
            atomicAdd(loss_sum, nll);
            atomicAdd(loss_cnt, 1.0f);
        }
    }
}

__global__ void k_loss_fin(float* dst, const float* s, const float* c)
{
    if (dst) *dst = *s / fmaxf(*c, 1.0f);
}

// ---------------- host orchestration ----------------
extern "C" void kernel_launch(void* const* d_in, const int* in_sizes, int n_in,
                              void* d_out, int out_size)
{
    const int*   idx      = (const int*)  d_in[0];
    const int*   targets  = (const int*)  d_in[1];
    const float* wte      = (const float*)d_in[2];
    const float* wpe      = (const float*)d_in[3];
    const float* ln1_w    = (const float*)d_in[4];
    const float* ln1_b    = (const float*)d_in[5];
    const float* qkv_w    = (const float*)d_in[6];
    const float* qkv_b    = (const float*)d_in[7];
    const float* proj_w   = (const float*)d_in[8];
    const float* proj_b   = (const float*)d_in[9];
    const float* ln2_w    = (const float*)d_in[10];
    const float* ln2_b    = (const float*)d_in[11];
    const float* fc_w     = (const float*)d_in[12];
    const float* fc_b     = (const float*)d_in[13];
    const float* fc2_w    = (const float*)d_in[14];
    const float* fc2_b    = (const float*)d_in[15];
    const float* lnf_w    = (const float*)d_in[16];
    const float* lnf_b    = (const float*)d_in[17];
    const float* head_w   = (const float*)d_in[18];

    float *x, *qkv, *lscratch, *lsum, *lcnt;
    uint32_t *hhi, *hlo, *ahi, *alo, *fhi, *flo, *whi, *wlo;
    uint32_t *qphi, *qplo, *kphi, *kplo, *vthi, *vtlo;
    cudaGetSymbolAddress((void**)&x,    g_x);
    cudaGetSymbolAddress((void**)&qkv,  g_qkv);
    cudaGetSymbolAddress((void**)&hhi,  g_h_hi);
    cudaGetSymbolAddress((void**)&hlo,  g_h_lo);
    cudaGetSymbolAddress((void**)&ahi,  g_att_hi);
    cudaGetSymbolAddress((void**)&alo,  g_att_lo);
    cudaGetSymbolAddress((void**)&fhi,  g_fch_hi);
    cudaGetSymbolAddress((void**)&flo,  g_fch_lo);
    cudaGetSymbolAddress((void**)&whi,  g_whi);
    cudaGetSymbolAddress((void**)&wlo,  g_wlo);
    cudaGetSymbolAddress((void**)&qphi, g_qphi);
    cudaGetSymbolAddress((void**)&qplo, g_qplo);
    cudaGetSymbolAddress((void**)&kphi, g_kphi);
    cudaGetSymbolAddress((void**)&kplo, g_kplo);
    cudaGetSymbolAddress((void**)&vthi, g_vthi);
    cudaGetSymbolAddress((void**)&vtlo, g_vtlo);
    cudaGetSymbolAddress((void**)&lscratch, g_logits_scratch);
    cudaGetSymbolAddress((void**)&lsum, g_loss_sum);
    cudaGetSymbolAddress((void**)&lcnt, g_loss_cnt);

    cudaFuncSetAttribute(k_gemm_bf,  cudaFuncAttributeMaxDynamicSharedMemorySize, GEMM_SMEM);
    cudaFuncSetAttribute(k_gemm_bf2, cudaFuncAttributeMaxDynamicSharedMemorySize, GEMM2_SMEM);
    cudaFuncSetAttribute(k_attn_mma, cudaFuncAttributeMaxDynamicSharedMemorySize, ATT_SMEM);

    float* logits = (out_size >= NBTV) ? (float*)d_out : lscratch;
    float* loss_dst = nullptr;
    if (out_size >= NBTV + 1)      loss_dst = (float*)d_out + NBTV;
    else if (out_size < NBTV)      loss_dst = (float*)d_out;

    dim3 attn_grid(NT / 64, NH, NB);
    dim3 split_grid(NT / 64, NH, NB);

    // launch order: ncu captures launch #4 -> QKV GEMM (l=0, new bf2 kernel)
    {
        dim3 blk(32, 8);
        k_wsplit_all<<<WS_TOTAL_BLOCKS, blk>>>(qkv_w, proj_w, fc_w, fc2_w, head_w, whi, wlo);  // 1
    }
    {
        int n = NBT * NC;
        k_embed<<<(n + 255) / 256, 256>>>(idx, wte, wpe, x);   // 2
    }
    k_layernorm_p<<<NBT / 4, 128>>>(x, ln1_w, ln1_b, hhi, hlo);  // 3
    {
        dim3 grid(NBT / 256, (3 * NC + 127) / 128);
        k_gemm_bf2<<<grid, 256, GEMM2_SMEM>>>(hhi, hlo,          // 4 <- profiled
            whi + OFF_QKV, wlo + OFF_QKV,
            qkv_b, nullptr, qkv, nullptr, nullptr,
            NBT, 3 * NC, NC / 2, 0);
    }
    k_zero_loss<<<1, 1>>>(lsum, lcnt);                           // 5

    for (int l = 0; l < NL; l++) {
        if (l > 0) {
            k_layernorm_p<<<NBT / 4, 128>>>(x, ln1_w + l * NC, ln1_b + l * NC, hhi, hlo);
            dim3 grid(NBT / 256, (3 * NC + 127) / 128);
            k_gemm_bf2<<<grid, 256, GEMM2_SMEM>>>(hhi, hlo,
                whi + OFF_QKV + l * SZ_QKV, wlo + OFF_QKV + l * SZ_QKV,
                qkv_b + l * 3 * NC, nullptr, qkv, nullptr, nullptr,
                NBT, 3 * NC, NC / 2, 0);
        }
        k_qkvsplit<<<split_grid, 128>>>(qkv, qphi, qplo, kphi, kplo, vthi, vtlo);
        k_attn_mma<<<attn_grid, 128, ATT_SMEM>>>(qphi, qplo, kphi, kplo, vthi, vtlo, ahi, alo);
        {
            dim3 grid(NBT / 128, (NC + 127) / 128);
            k_gemm_bf<<<grid, 256, GEMM_SMEM>>>(ahi, alo,
                whi + OFF_PROJ + l * SZ_PROJ, wlo + OFF_PROJ + l * SZ_PROJ,
                proj_b + l * NC, x, x, nullptr, nullptr,
                NBT, NC, NC / 2, 0);
        }
        k_layernorm_p<<<NBT / 4, 128>>>(x, ln2_w + l * NC, ln2_b + l * NC, hhi, hlo);
        {
            dim3 grid(NBT / 256, (4 * NC + 127) / 128);
            k_gemm_bf2<<<grid, 256, GEMM2_SMEM>>>(hhi, hlo,
                whi + OFF_FC + l * SZ_FC, wlo + OFF_FC + l * SZ_FC,
                fc_b + l * 4 * NC, nullptr, nullptr, fhi, flo,
                NBT, 4 * NC, NC / 2, 1);
        }
        {
            dim3 grid(NBT / 128, (NC + 127) / 128);
            k_gemm_bf<<<grid, 256, GEMM_SMEM>>>(fhi, flo,
                whi + OFF_FC2 + l * SZ_FC2, wlo + OFF_FC2 + l * SZ_FC2,
                fc2_b + l * NC, x, x, nullptr, nullptr,
                NBT, NC, 4 * NC / 2, 0);
        }
    }

    k_layernorm_p<<<NBT / 4, 128>>>(x, lnf_w, lnf_b, hhi, hlo);

    {
        dim3 grid(NBT / 256, (NV + 127) / 128);
        k_gemm_bf2<<<grid, 256, GEMM2_SMEM>>>(hhi, hlo,
            whi + OFF_HEAD, wlo + OFF_HEAD,
            nullptr, nullptr, logits, nullptr, nullptr,
            NBT, NV, NC / 2, 0);
    }

    k_loss_rows<<<NBT, 256>>>(logits, targets, lsum, lcnt);
    k_loss_fin<<<1, 1>>>(loss_dst, lsum, lcnt);
}

// round 15
// speedup vs baseline: 1.0697x; 1.0697x over previous
#include <cuda_runtime.h>
#include <math.h>
#include <stdint.h>

// ---------------- problem constants ----------------
#define NB   4
#define NT   1024
#define NC   768
#define NH   12
#define NHD  64
#define NL   12
#define NV   50257
#define NBT  (NB*NT)     // 4096
#define NBTV (NBT*NV)

// weight plane offsets (uint32 units, transposed [N][K/2] per matrix)
#define OFF_QKV  0LL
#define SZ_QKV   (2304LL*384)
#define OFF_PROJ (OFF_QKV + 12*SZ_QKV)
#define SZ_PROJ  (768LL*384)
#define OFF_FC   (OFF_PROJ + 12*SZ_PROJ)
#define SZ_FC    (3072LL*384)
#define OFF_FC2  (OFF_FC + 12*SZ_FC)
#define SZ_FC2   (768LL*1536)
#define OFF_HEAD (OFF_FC2 + 12*SZ_FC2)
#define SZ_HEAD  (50257LL*384)
#define W_TOTAL  (OFF_HEAD + SZ_HEAD)

// ---------------- scratch ----------------
__device__ float    g_x   [NBT*NC];
__device__ float    g_qkv [NBT*3*NC];
__device__ uint32_t g_h_hi [NBT*NC/2];
__device__ uint32_t g_h_lo [NBT*NC/2];
__device__ uint32_t g_att_hi[NBT*NC/2];
__device__ uint32_t g_att_lo[NBT*NC/2];
__device__ uint32_t g_fch_hi[NBT*4*NC/2];
__device__ uint32_t g_fch_lo[NBT*4*NC/2];
__device__ uint32_t g_whi[W_TOTAL];
__device__ uint32_t g_wlo[W_TOTAL];
// packed attention operand planes: Q/K rows [bh][t][32w], Vt [bh][d][512w]
#define QK_WORDS (NB*NH*NT*32)
__device__ uint32_t g_qphi[QK_WORDS];
__device__ uint32_t g_qplo[QK_WORDS];
__device__ uint32_t g_kphi[QK_WORDS];
__device__ uint32_t g_kplo[QK_WORDS];
__device__ uint32_t g_vthi[QK_WORDS];
__device__ uint32_t g_vtlo[QK_WORDS];
__device__ float    g_logits_scratch[NBTV];
__device__ float    g_loss_sum;
__device__ float    g_loss_cnt;

__device__ __forceinline__ float gelu_f(float u) {
    return 0.5f * u * (1.0f + tanhf(0.7978845608028654f * (u + 0.044715f * u * u * u)));
}

__device__ __forceinline__ uint32_t pack_bf2(float even, float odd) {
    uint32_t r;
    asm("cvt.rn.bf16x2.f32 %0, %1, %2;" : "=r"(r) : "f"(odd), "f"(even));
    return r;
}
__device__ __forceinline__ uint32_t lo_pair(uint32_t hp, float even, float odd) {
    float e_h = __uint_as_float(hp << 16);
    float o_h = __uint_as_float(hp & 0xffff0000u);
    return pack_bf2(even - e_h, odd - o_h);
}

__device__ __forceinline__ void mma_bf16(float* c, const uint32_t* a, const uint32_t* b) {
    asm volatile(
        "mma.sync.aligned.m16n8k16.row.col.f32.bf16.bf16.f32 "
        "{%0,%1,%2,%3}, {%4,%5,%6,%7}, {%8,%9}, {%0,%1,%2,%3};"
        : "+f"(c[0]), "+f"(c[1]), "+f"(c[2]), "+f"(c[3])
        : "r"(a[0]), "r"(a[1]), "r"(a[2]), "r"(a[3]), "r"(b[0]), "r"(b[1]));
}

__device__ __forceinline__ uint32_t smem_u32(const void* p) {
    uint32_t a;
    asm("{ .reg .u64 t; cvta.to.shared.u64 t, %1; cvt.u32.u64 %0, t; }" : "=r"(a) : "l"(p));
    return a;
}
__device__ __forceinline__ void cpa16(uint32_t saddr, const void* g, uint32_t srcsz) {
    asm volatile("cp.async.cg.shared.global [%0], [%1], 16, %2;"
                 :: "r"(saddr), "l"(g), "r"(srcsz) : "memory");
}
#define CPA_COMMIT() asm volatile("cp.async.commit_group;" ::: "memory")
#define CPA_WAIT4()  asm volatile("cp.async.wait_group 4;" ::: "memory")
#define CPA_WAIT1()  asm volatile("cp.async.wait_group 1;" ::: "memory")
#define CPA_WAIT0()  asm volatile("cp.async.wait_group 0;" ::: "memory")

__device__ __forceinline__ void ldsm4(uint32_t* r, uint32_t addr) {
    asm volatile("ldmatrix.sync.aligned.m8n8.x4.shared.b16 {%0,%1,%2,%3}, [%4];"
                 : "=r"(r[0]), "=r"(r[1]), "=r"(r[2]), "=r"(r[3]) : "r"(addr));
}

// ---------------- small kernels ----------------
__global__ void k_zero_loss(float* s, float* c) { *s = 0.f; *c = 0.f; }

__global__ void k_embed(const int* __restrict__ idx,
                        const float* __restrict__ wte,
                        const float* __restrict__ wpe,
                        float* __restrict__ x)
{
    int i = blockIdx.x * blockDim.x + threadIdx.x;
    if (i >= NBT * NC) return;
    int c  = i % NC;
    int bt = i / NC;
    int t  = bt % NT;
    x[i] = wte[(long long)idx[bt] * NC + c] + wpe[t * NC + c];
}

// ---- single-launch weight transpose+split over all 49 matrices ----
#define WS_TOTAL_BLOCKS 60324
__global__ void k_wsplit_all(const float* __restrict__ qkv_w,
                             const float* __restrict__ proj_w,
                             const float* __restrict__ fc_w,
                             const float* __restrict__ fc2_w,
                             const float* __restrict__ head_w,
                             uint32_t* __restrict__ Whi,
                             uint32_t* __restrict__ Wlo)
{
    __shared__ uint32_t shi[32][33];
    __shared__ uint32_t slo[32][33];

    int bid = blockIdx.x;
    const float* W;
    long long dst;
    int K, N, ntn, t;
    if (bid < 10368) {
        int m = bid / 864; t = bid % 864;
        W = qkv_w + (long long)m * 768 * 2304; dst = OFF_QKV + m * SZ_QKV;
        K = 768; N = 2304; ntn = 72;
    } else if (bid < 13824) {
        bid -= 10368; int m = bid / 288; t = bid % 288;
        W = proj_w + (long long)m * 768 * 768; dst = OFF_PROJ + m * SZ_PROJ;
        K = 768; N = 768; ntn = 24;
    } else if (bid < 27648) {
        bid -= 13824; int m = bid / 1152; t = bid % 1152;
        W = fc_w + (long long)m * 768 * 3072; dst = OFF_FC + m * SZ_FC;
        K = 768; N = 3072; ntn = 96;
    } else if (bid < 41472) {
        bid -= 27648; int m = bid / 1152; t = bid % 1152;
        W = fc2_w + (long long)m * 3072 * 768; dst = OFF_FC2 + m * SZ_FC2;
        K = 3072; N = 768; ntn = 24;
    } else {
        t = bid - 41472;
        W = head_w; dst = OFF_HEAD;
        K = 768; N = NV; ntn = 1571;
    }
    const int K2 = K >> 1;
    const int n0  = (t % ntn) * 32;
    const int kp0 = (t / ntn) * 32;
    const int tx = threadIdx.x;
    const int ty = threadIdx.y;

    #pragma unroll
    for (int r = ty; r < 32; r += 8) {
        int kp = kp0 + r;
        int n  = n0 + tx;
        if (kp < K2 && n < N) {
            float w0 = W[(long long)(2 * kp) * N + n];
            float w1 = W[(long long)(2 * kp + 1) * N + n];
            uint32_t hp = pack_bf2(w0, w1);
            shi[r][tx] = hp;
            slo[r][tx] = lo_pair(hp, w0, w1);
        }
    }
    __syncthreads();
    #pragma unroll
    for (int r = ty; r < 32; r += 8) {
        int n  = n0 + r;
        int kp = kp0 + tx;
        if (kp < K2 && n < N) {
            long long o = dst + (long long)n * K2 + kp;
            Whi[o] = shi[tx][r];
            Wlo[o] = slo[tx][r];
        }
    }
}

// ---- warp-per-row layernorm -> packed planes ----
__global__ __launch_bounds__(128)
void k_layernorm_p(const float* __restrict__ x,
                   const float* __restrict__ w,
                   const float* __restrict__ b,
                   uint32_t* __restrict__ hhi,
                   uint32_t* __restrict__ hlo)
{
    const int lane = threadIdx.x & 31;
    const int row = blockIdx.x * 4 + (threadIdx.x >> 5);
    const float* xr = x + (long long)row * NC;

    float4 v[6];
    #pragma unroll
    for (int j = 0; j < 6; j++)
        v[j] = *(const float4*)(xr + (j * 32 + lane) * 4);

    float s = 0.f;
    #pragma unroll
    for (int j = 0; j < 6; j++) s += v[j].x + v[j].y + v[j].z + v[j].w;
    #pragma unroll
    for (int off = 16; off > 0; off >>= 1) s += __shfl_xor_sync(0xffffffffu, s, off);
    const float mu = s * (1.0f / NC);

    float var = 0.f;
    #pragma unroll
    for (int j = 0; j < 6; j++) {
        float a0 = v[j].x - mu, a1 = v[j].y - mu, a2 = v[j].z - mu, a3 = v[j].w - mu;
        var += a0 * a0 + a1 * a1 + a2 * a2 + a3 * a3;
    }
    #pragma unroll
    for (int off = 16; off > 0; off >>= 1) var += __shfl_xor_sync(0xffffffffu, var, off);
    const float rstd = rsqrtf(var * (1.0f / NC) + 1e-5f);

    const long long base = (long long)row * (NC / 2);
    #pragma unroll
    for (int j = 0; j < 6; j++) {
        const int c = (j * 32 + lane) * 4;
        float n0 = (v[j].x - mu) * rstd * w[c]     + b[c];
        float n1 = (v[j].y - mu) * rstd * w[c + 1] + b[c + 1];
        float n2 = (v[j].z - mu) * rstd * w[c + 2] + b[c + 2];
        float n3 = (v[j].w - mu) * rstd * w[c + 3] + b[c + 3];
        uint2 hp, lp;
        hp.x = pack_bf2(n0, n1); lp.x = lo_pair(hp.x, n0, n1);
        hp.y = pack_bf2(n2, n3); lp.y = lo_pair(hp.y, n2, n3);
        *(uint2*)(hhi + base + (c >> 1)) = hp;
        *(uint2*)(hlo + base + (c >> 1)) = lp;
    }
}

// ---- per-layer QKV -> packed attention planes (convert once) ----
__global__ __launch_bounds__(128)
void k_qkvsplit(const float* __restrict__ qkv,
                uint32_t* __restrict__ qhi, uint32_t* __restrict__ qlo,
                uint32_t* __restrict__ khi, uint32_t* __restrict__ klo,
                uint32_t* __restrict__ vthi, uint32_t* __restrict__ vtlo)
{
    __shared__ float stage[64][68];
    const int t0 = blockIdx.x * 64;
    const int h  = blockIdx.y;
    const int b  = blockIdx.z;
    const int tid = threadIdx.x;
    const int r = tid >> 1;
    const int hc = tid & 1;
    const long long bh = (long long)(b * NH + h);
    const float* base = qkv + (long long)b * NT * 3 * NC;

    {
        const float* qrow = base + (long long)(t0 + r) * (3 * NC) + h * NHD + hc * 32;
        const float* krow = qrow + NC;
        const long long out = (bh * NT + t0 + r) * 32 + hc * 16;
        #pragma unroll
        for (int c4 = 0; c4 < 4; c4++) {
            uint4 qh, ql, kh, kl;
            uint32_t* qhp = &qh.x; uint32_t* qlp = &ql.x;
            uint32_t* khp = &kh.x; uint32_t* klp = &kl.x;
            #pragma unroll
            for (int e = 0; e < 4; e++) {
                const int wd = c4 * 4 + e;
                float qe = qrow[2 * wd], qo = qrow[2 * wd + 1];
                qhp[e] = pack_bf2(qe, qo); qlp[e] = lo_pair(qhp[e], qe, qo);
                float ke = krow[2 * wd], ko = krow[2 * wd + 1];
                khp[e] = pack_bf2(ke, ko); klp[e] = lo_pair(khp[e], ke, ko);
            }
            *(uint4*)(qhi + out + c4 * 4) = qh;
            *(uint4*)(qlo + out + c4 * 4) = ql;
            *(uint4*)(khi + out + c4 * 4) = kh;
            *(uint4*)(klo + out + c4 * 4) = kl;
        }
    }

    {
        const float* vrow = base + (long long)(t0 + r) * (3 * NC) + 2 * NC + h * NHD + hc * 32;
        #pragma unroll
        for (int j = 0; j < 8; j++)
            *(float4*)(&stage[r][hc * 32 + j * 4]) = *(const float4*)(vrow + j * 4);
    }
    __syncthreads();

    {
        const int d = r;
        const long long out = (bh * NHD + d) * (NT / 2) + t0 / 2 + hc * 16;
        #pragma unroll
        for (int c4 = 0; c4 < 4; c4++) {
            uint4 vh, vl;
            uint32_t* vhp = &vh.x; uint32_t* vlp = &vl.x;
            #pragma unroll
            for (int e = 0; e < 4; e++) {
                const int tok = hc * 32 + (c4 * 4 + e) * 2;
                float ve = stage[tok][d], vo = stage[tok + 1][d];
                vhp[e] = pack_bf2(ve, vo); vlp[e] = lo_pair(vhp[e], ve, vo);
            }
            *(uint4*)(vthi + out + c4 * 4) = vh;
            *(uint4*)(vtlo + out + c4 * 4) = vl;
        }
    }
}

// ---------------- split-bf16 GEMM, 128x128 tile (proj/fc2) ----------------
#define GEMM_SMEM 98304

__global__ __launch_bounds__(256, 2)
void k_gemm_bf(const uint32_t* __restrict__ Ahi, const uint32_t* __restrict__ Alo,
               const uint32_t* __restrict__ Bhi, const uint32_t* __restrict__ Blo,
               const float* __restrict__ bias, const float* __restrict__ res,
               float* __restrict__ Cf,
               uint32_t* __restrict__ Chi, uint32_t* __restrict__ Clo,
               int M, int N, int K2, int act)
{
    extern __shared__ uint32_t smw[];
    const uint32_t sbase = smem_u32(smw);

    const int tid  = threadIdx.x;
    const int lane = tid & 31;
    const int w    = tid >> 5;
    const int bm   = blockIdx.x * 128;
    const int bn   = blockIdx.y * 128;
    const int wm   = (w & 1) * 64;
    const int wn   = (w >> 1) * 32;
    const int g    = lane >> 2;
    const int tig  = lane & 3;

    const int m    = tid >> 1;
    const int half = tid & 1;
    const uint32_t swoff = (uint32_t)((half ^ ((m >> 2) & 1)) << 4);
    const long long aoff = (long long)(bm + m) * K2 + half * 4;
    const int bn_row = (bn + m < N) ? (bn + m) : (N - 1);
    const long long boff = (long long)bn_row * K2 + half * 4;
    const uint32_t bsz = (bn + m < N) ? 16u : 0u;

    const int l15 = lane & 15;
    const uint32_t a_sw = (uint32_t)((((lane >> 4) << 2) ^ (((l15 >> 2) & 1) << 2)) << 2);
    const uint32_t a_base = sbase + (uint32_t)(wm + l15) * 32 + a_sw;
    const int l8 = lane & 7;
    const uint32_t b_sw = (uint32_t)(((((lane >> 3) & 1) << 2) ^ (((l8 >> 2) & 1) << 2)) << 2);
    const uint32_t b_base = sbase + 8192u +
        (uint32_t)(wn + ((lane >> 4) & 1) * 8 + l8) * 32 + b_sw;

    float acc[16][4];
    #pragma unroll
    for (int i = 0; i < 16; i++)
        #pragma unroll
        for (int j = 0; j < 4; j++) acc[i][j] = 0.f;

#define ISSUE_STAGE(S_) do {                                              \
        const int _buf = (S_) % 6;                                        \
        const uint32_t _so = sbase + _buf * 16384 + m * 32 + swoff;       \
        const long long _ko = (long long)(S_) * 8;                        \
        cpa16(_so,         Ahi + aoff + _ko, 16u);                        \
        cpa16(_so + 4096,  Alo + aoff + _ko, 16u);                        \
        cpa16(_so + 8192,  Bhi + boff + _ko, bsz);                        \
        cpa16(_so + 12288, Blo + boff + _ko, bsz);                        \
        CPA_COMMIT();                                                     \
    } while (0)

    const int S = K2 >> 3;
    ISSUE_STAGE(0);
    ISSUE_STAGE(1);
    ISSUE_STAGE(2);
    ISSUE_STAGE(3);
    ISSUE_STAGE(4);

    for (int s = 0; s < S; s++) {
        CPA_WAIT4();
        __syncthreads();
        if (s + 5 < S) { ISSUE_STAGE(s + 5); } else { CPA_COMMIT(); }

        const uint32_t stoff = (uint32_t)((s % 6) * 16384);

        uint32_t bh[8], bl[8];
        ldsm4(bh,     b_base + stoff);
        ldsm4(bh + 4, b_base + stoff + 512);
        ldsm4(bl,     b_base + stoff + 4096);
        ldsm4(bl + 4, b_base + stoff + 4096 + 512);

        #pragma unroll
        for (int mt = 0; mt < 4; mt++) {
            uint32_t ah[4], al[4];
            ldsm4(ah, a_base + stoff + mt * 512);
            ldsm4(al, a_base + stoff + mt * 512 + 4096);
            #pragma unroll
            for (int nt = 0; nt < 4; nt++) {
                mma_bf16(acc[mt * 4 + nt], ah, bh + nt * 2);
                mma_bf16(acc[mt * 4 + nt], ah, bl + nt * 2);
                mma_bf16(acc[mt * 4 + nt], al, bh + nt * 2);
            }
        }
    }
#undef ISSUE_STAGE

    const bool evenN = ((N & 1) == 0);
    #pragma unroll
    for (int mt = 0; mt < 4; mt++) {
        #pragma unroll
        for (int nt = 0; nt < 4; nt++) {
            const float* c = acc[mt * 4 + nt];
            const int n = bn + wn + nt * 8 + tig * 2;
            #pragma unroll
            for (int hf = 0; hf < 2; hf++) {
                const int mm = bm + wm + mt * 16 + g + hf * 8;
                float v0 = c[hf * 2 + 0];
                float v1 = c[hf * 2 + 1];
                if (act == 1) {
                    if (bias) { v0 += bias[n]; v1 += bias[n + 1]; }
                    v0 = gelu_f(v0); v1 = gelu_f(v1);
                    uint32_t hp = pack_bf2(v0, v1);
                    long long o = (long long)mm * (N >> 1) + (n >> 1);
                    Chi[o] = hp;
                    Clo[o] = lo_pair(hp, v0, v1);
                } else {
                    const long long rowoff = (long long)mm * N;
                    if (n + 1 < N) {
                        if (bias) { v0 += bias[n]; v1 += bias[n + 1]; }
                        if (res)  { v0 += res[rowoff + n]; v1 += res[rowoff + n + 1]; }
                        if (evenN) {
                            *(float2*)(Cf + rowoff + n) = make_float2(v0, v1);
                        } else {
                            Cf[rowoff + n]     = v0;
                            Cf[rowoff + n + 1] = v1;
                        }
                    } else if (n < N) {
                        if (bias) v0 += bias[n];
                        if (res)  v0 += res[rowoff + n];
                        Cf[rowoff + n] = v0;
                    }
                }
            }
        }
    }
}

// ---------------- split-bf16 GEMM, 256x128 tile, 512 threads --------------
// 16 warps (4m x 4n), warp tile 64x32 (identical per-warp code to k_gemm_bf
// -> ~128 regs, no spill). 1 CTA/SM. Stage 24KB: Ahi 8K | Alo 8K | Bhi 4K |
// Blo 4K; 6 stages = 144KB.
#define GEMM5_SMEM 147456

__global__ __launch_bounds__(512, 1)
void k_gemm_bf512(const uint32_t* __restrict__ Ahi, const uint32_t* __restrict__ Alo,
                  const uint32_t* __restrict__ Bhi, const uint32_t* __restrict__ Blo,
                  const float* __restrict__ bias, const float* __restrict__ res,
                  float* __restrict__ Cf,
                  uint32_t* __restrict__ Chi, uint32_t* __restrict__ Clo,
                  int M, int N, int K2, int act)
{
    extern __shared__ uint32_t smw[];
    const uint32_t sbase = smem_u32(smw);

    const int tid  = threadIdx.x;
    const int lane = tid & 31;
    const int w    = tid >> 5;            // 0..15
    const int bm   = blockIdx.x * 256;
    const int bn   = blockIdx.y * 128;
    const int wm   = (w & 3) * 64;
    const int wn   = (w >> 2) * 32;
    const int g    = lane >> 2;
    const int tig  = lane & 3;

    // cp.async mapping: A rows 0..255 (2 thr/row); B rows 0..127, plane by tid>>8
    const int a_r   = tid >> 1;
    const int half  = tid & 1;
    const uint32_t aswoff = (uint32_t)((half ^ ((a_r >> 2) & 1)) << 4);
    const long long aoff = (long long)(bm + a_r) * K2 + half * 4;
    const int b_t   = tid & 255;
    const int b_r   = b_t >> 1;
    const int b_h   = b_t & 1;
    const int plane = tid >> 8;           // 0 = hi, 1 = lo
    const uint32_t bswoff = (uint32_t)((b_h ^ ((b_r >> 2) & 1)) << 4);
    const int bn_row = (bn + b_r < N) ? (bn + b_r) : (N - 1);
    const long long boff = (long long)bn_row * K2 + b_h * 4;
    const uint32_t bsz = (bn + b_r < N) ? 16u : 0u;
    const uint32_t* Bpl = plane ? Blo : Bhi;
    const uint32_t bdst = 16384u + (uint32_t)plane * 4096u + (uint32_t)b_r * 32 + bswoff;

    // ldmatrix bases
    const int l15 = lane & 15;
    const uint32_t a_sw = (uint32_t)((((lane >> 4) << 2) ^ (((l15 >> 2) & 1) << 2)) << 2);
    const uint32_t a_base = sbase + (uint32_t)(wm + l15) * 32 + a_sw;
    const int l8 = lane & 7;
    const uint32_t b_sw = (uint32_t)(((((lane >> 3) & 1) << 2) ^ (((l8 >> 2) & 1) << 2)) << 2);
    const uint32_t b_base = sbase + 16384u +
        (uint32_t)(wn + ((lane >> 4) & 1) * 8 + l8) * 32 + b_sw;

    float acc[16][4];
    #pragma unroll
    for (int i = 0; i < 16; i++)
        #pragma unroll
        for (int j = 0; j < 4; j++) acc[i][j] = 0.f;

#define ISSUE_STAGE5(S_) do {                                             \
        const int _buf = (S_) % 6;                                        \
        const uint32_t _sb = sbase + _buf * 24576;                        \
        const long long _ko = (long long)(S_) * 8;                        \
        cpa16(_sb + a_r * 32 + aswoff,        Ahi + aoff + _ko, 16u);     \
        cpa16(_sb + 8192 + a_r * 32 + aswoff, Alo + aoff + _ko, 16u);     \
        cpa16(_sb + bdst,                     Bpl + boff + _ko, bsz);     \
        CPA_COMMIT();                                                     \
    } while (0)

    const int S = K2 >> 3;
    ISSUE_STAGE5(0);
    ISSUE_STAGE5(1);
    ISSUE_STAGE5(2);
    ISSUE_STAGE5(3);
    ISSUE_STAGE5(4);

    for (int s = 0; s < S; s++) {
        CPA_WAIT4();
        __syncthreads();
        if (s + 5 < S) { ISSUE_STAGE5(s + 5); } else { CPA_COMMIT(); }

        const uint32_t stoff = (uint32_t)((s % 6) * 24576);

        uint32_t bh[8], bl[8];
        ldsm4(bh,     b_base + stoff);
        ldsm4(bh + 4, b_base + stoff + 512);
        ldsm4(bl,     b_base + stoff + 4096);
        ldsm4(bl + 4, b_base + stoff + 4096 + 512);

        #pragma unroll
        for (int mt = 0; mt < 4; mt++) {
            uint32_t ah[4], al[4];
            ldsm4(ah, a_base + stoff + mt * 512);
            ldsm4(al, a_base + stoff + mt * 512 + 8192);
            #pragma unroll
            for (int nt = 0; nt < 4; nt++) {
                mma_bf16(acc[mt * 4 + nt], ah, bh + nt * 2);
                mma_bf16(acc[mt * 4 + nt], ah, bl + nt * 2);
                mma_bf16(acc[mt * 4 + nt], al, bh + nt * 2);
            }
        }
    }
#undef ISSUE_STAGE5

    const bool evenN = ((N & 1) == 0);
    #pragma unroll
    for (int mt = 0; mt < 4; mt++) {
        #pragma unroll
        for (int nt = 0; nt < 4; nt++) {
            const float* c = acc[mt * 4 + nt];
            const int n = bn + wn + nt * 8 + tig * 2;
            #pragma unroll
            for (int hf = 0; hf < 2; hf++) {
                const int mm = bm + wm + mt * 16 + g + hf * 8;
                float v0 = c[hf * 2 + 0];
                float v1 = c[hf * 2 + 1];
                if (act == 1) {
                    if (bias) { v0 += bias[n]; v1 += bias[n + 1]; }
                    v0 = gelu_f(v0); v1 = gelu_f(v1);
                    uint32_t hp = pack_bf2(v0, v1);
                    long long o = (long long)mm * (N >> 1) + (n >> 1);
                    Chi[o] = hp;
                    Clo[o] = lo_pair(hp, v0, v1);
                } else {
                    const long long rowoff = (long long)mm * N;
                    if (n + 1 < N) {
                        if (bias) { v0 += bias[n]; v1 += bias[n + 1]; }
                        if (res)  { v0 += res[rowoff + n]; v1 += res[rowoff + n + 1]; }
                        if (evenN) {
                            *(float2*)(Cf + rowoff + n) = make_float2(v0, v1);
                        } else {
                            Cf[rowoff + n]     = v0;
                            Cf[rowoff + n + 1] = v1;
                        }
                    } else if (n < N) {
                        if (bias) v0 += bias[n];
                        if (res)  v0 += res[rowoff + n];
                        Cf[rowoff + n] = v0;
                    }
                }
            }
        }
    }
}

// ---------------- tensor-core flash attention (precomputed planes) --------
#define ATT_SMEM 81920

__global__ __launch_bounds__(128)
void k_attn_mma(const uint32_t* __restrict__ qphi, const uint32_t* __restrict__ qplo,
                const uint32_t* __restrict__ kphi, const uint32_t* __restrict__ kplo,
                const uint32_t* __restrict__ vthi, const uint32_t* __restrict__ vtlo,
                uint32_t* __restrict__ yhi, uint32_t* __restrict__ ylo)
{
    extern __shared__ char smatt[];
    const uint32_t sb = smem_u32(smatt);

    const int tid  = threadIdx.x;
    const int lane = tid & 31;
    const int w    = tid >> 5;
    const int g    = lane >> 2;
    const int tig  = lane & 3;
    const int q0   = blockIdx.x * 64;
    const int h    = blockIdx.y;
    const int b    = blockIdx.z;
    const long long bh = (long long)(b * NH + h);

    const int r  = tid >> 1;
    const int cb = (tid & 1) * 4;
    const uint32_t rsw = (uint32_t)(r & 7);

    {
        const long long grow = (bh * NT + q0 + r) * 32;
        const uint32_t so = sb + (uint32_t)(r * 128);
        #pragma unroll
        for (int cc = 0; cc < 4; cc++) {
            const int c = cb + cc;
            const uint32_t sw = (uint32_t)((c ^ rsw) << 4);
            cpa16(so + sw,        qphi + grow + c * 4, 16u);
            cpa16(so + 8192 + sw, qplo + grow + c * 4, 16u);
        }
        CPA_COMMIT();
    }

#define ISSUE_KV(J_) do {                                                   \
        const uint32_t _bo = sb + 16384u + (uint32_t)(((J_) & 1) * 32768);  \
        const long long _kg = (bh * NT + (long long)(J_) * 64 + r) * 32;    \
        const long long _vg = (bh * NHD + r) * (NT / 2) + (long long)(J_) * 32; \
        const uint32_t _so = _bo + (uint32_t)(r * 128);                     \
        _Pragma("unroll")                                                   \
        for (int cc = 0; cc < 4; cc++) {                                    \
            const int c = cb + cc;                                          \
            const uint32_t sw = (uint32_t)((c ^ rsw) << 4);                 \
            cpa16(_so + sw,         kphi + _kg + c * 4, 16u);               \
            cpa16(_so + 8192 + sw,  kplo + _kg + c * 4, 16u);               \
            cpa16(_so + 16384 + sw, vthi + _vg + c * 4, 16u);               \
            cpa16(_so + 24576 + sw, vtlo + _vg + c * 4, 16u);               \
        }                                                                   \
        CPA_COMMIT();                                                       \
    } while (0)

    const int ntiles = blockIdx.x + 1;
    ISSUE_KV(0);

    float oC[8][4];
    #pragma unroll
    for (int i = 0; i < 8; i++)
        #pragma unroll
        for (int j = 0; j < 4; j++) oC[i][j] = 0.f;
    float mi0 = -1e30f, mi1 = -1e30f, li0 = 0.f, li1 = 0.f;

    const int qw = w * 16;
    const int r0 = q0 + qw + g;
    const int r1 = r0 + 8;

    for (int tj = 0; tj < ntiles; tj++) {
        const int j0 = tj * 64;
        if (tj + 1 < ntiles) { ISSUE_KV(tj + 1); CPA_WAIT1(); }
        else                 { CPA_WAIT0(); }
        __syncthreads();

        const uint32_t kb = sb + 16384u + (uint32_t)((tj & 1) * 32768);

        float sC[8][4];
        #pragma unroll
        for (int i = 0; i < 8; i++)
            #pragma unroll
            for (int j = 0; j < 4; j++) sC[i][j] = 0.f;

        #pragma unroll
        for (int ks = 0; ks < 4; ks++) {
            const int ar = qw + (lane & 15);
            const uint32_t aaddr = sb + (uint32_t)(ar * 128 +
                (((2 * ks + (lane >> 4)) ^ (ar & 7)) << 4));
            uint32_t qa_h[4], qa_l[4];
            ldsm4(qa_h, aaddr);
            ldsm4(qa_l, aaddr + 8192);
            #pragma unroll
            for (int np = 0; np < 4; np++) {
                const int br = np * 16 + ((lane >> 4) & 1) * 8 + (lane & 7);
                const uint32_t baddr = kb + (uint32_t)(br * 128 +
                    (((2 * ks + ((lane >> 3) & 1)) ^ (br & 7)) << 4));
                uint32_t kb_h[4], kb_l[4];
                ldsm4(kb_h, baddr);
                ldsm4(kb_l, baddr + 8192);
                mma_bf16(sC[2*np],   qa_h, kb_h);
                mma_bf16(sC[2*np],   qa_h, kb_l);
                mma_bf16(sC[2*np],   qa_l, kb_h);
                mma_bf16(sC[2*np+1], qa_h, kb_h + 2);
                mma_bf16(sC[2*np+1], qa_h, kb_l + 2);
                mma_bf16(sC[2*np+1], qa_l, kb_h + 2);
            }
        }

        const bool diag = (tj + 1 == ntiles);
        #pragma unroll
        for (int nt = 0; nt < 8; nt++) {
            const int c0 = j0 + nt * 8 + tig * 2;
            if (diag) {
                sC[nt][0] = (c0     <= r0) ? sC[nt][0] * 0.125f : -1e30f;
                sC[nt][1] = (c0 + 1 <= r0) ? sC[nt][1] * 0.125f : -1e30f;
                sC[nt][2] = (c0     <= r1) ? sC[nt][2] * 0.125f : -1e30f;
                sC[nt][3] = (c0 + 1 <= r1) ? sC[nt][3] * 0.125f : -1e30f;
            } else {
                sC[nt][0] *= 0.125f; sC[nt][1] *= 0.125f;
                sC[nt][2] *= 0.125f; sC[nt][3] *= 0.125f;
            }
        }

        float m0 = -1e30f, m1 = -1e30f;
        #pragma unroll
        for (int nt = 0; nt < 8; nt++) {
            m0 = fmaxf(m0, fmaxf(sC[nt][0], sC[nt][1]));
            m1 = fmaxf(m1, fmaxf(sC[nt][2], sC[nt][3]));
        }
        m0 = fmaxf(m0, __shfl_xor_sync(0xffffffffu, m0, 1));
        m0 = fmaxf(m0, __shfl_xor_sync(0xffffffffu, m0, 2));
        m1 = fmaxf(m1, __shfl_xor_sync(0xffffffffu, m1, 1));
        m1 = fmaxf(m1, __shfl_xor_sync(0xffffffffu, m1, 2));
        const float mn0 = fmaxf(mi0, m0), mn1 = fmaxf(mi1, m1);
        const float corr0 = __expf(mi0 - mn0), corr1 = __expf(mi1 - mn1);

        float rs0 = 0.f, rs1 = 0.f;
        uint32_t pa_h[4][4], pa_l[4][4];
        #pragma unroll
        for (int nt = 0; nt < 8; nt++) {
            float p0 = __expf(sC[nt][0] - mn0);
            float p1 = __expf(sC[nt][1] - mn0);
            float p2 = __expf(sC[nt][2] - mn1);
            float p3 = __expf(sC[nt][3] - mn1);
            rs0 += p0 + p1; rs1 += p2 + p3;
            const int ks = nt >> 1;
            const int rb = (nt & 1) * 2;
            uint32_t u01 = pack_bf2(p0, p1);
            uint32_t u23 = pack_bf2(p2, p3);
            pa_h[ks][rb]     = u01; pa_l[ks][rb]     = lo_pair(u01, p0, p1);
            pa_h[ks][rb + 1] = u23; pa_l[ks][rb + 1] = lo_pair(u23, p2, p3);
        }
        rs0 += __shfl_xor_sync(0xffffffffu, rs0, 1);
        rs0 += __shfl_xor_sync(0xffffffffu, rs0, 2);
        rs1 += __shfl_xor_sync(0xffffffffu, rs1, 1);
        rs1 += __shfl_xor_sync(0xffffffffu, rs1, 2);
        li0 = li0 * corr0 + rs0; mi0 = mn0;
        li1 = li1 * corr1 + rs1; mi1 = mn1;
        #pragma unroll
        for (int nt = 0; nt < 8; nt++) {
            oC[nt][0] *= corr0; oC[nt][1] *= corr0;
            oC[nt][2] *= corr1; oC[nt][3] *= corr1;
        }

        #pragma unroll
        for (int ks = 0; ks < 4; ks++) {
            #pragma unroll
            for (int np = 0; np < 4; np++) {
                const int br = np * 16 + ((lane >> 4) & 1) * 8 + (lane & 7);
                const uint32_t baddr = kb + 16384u + (uint32_t)(br * 128 +
                    (((2 * ks + ((lane >> 3) & 1)) ^ (br & 7)) << 4));
                uint32_t vb_h[4], vb_l[4];
                ldsm4(vb_h, baddr);
                ldsm4(vb_l, baddr + 8192);
                mma_bf16(oC[2*np],   pa_h[ks], vb_h);
                mma_bf16(oC[2*np],   pa_h[ks], vb_l);
                mma_bf16(oC[2*np],   pa_l[ks], vb_h);
                mma_bf16(oC[2*np+1], pa_h[ks], vb_h + 2);
                mma_bf16(oC[2*np+1], pa_h[ks], vb_l + 2);
                mma_bf16(oC[2*np+1], pa_l[ks], vb_h + 2);
            }
        }
        __syncthreads();
    }
#undef ISSUE_KV

    const float inv0 = 1.0f / li0, inv1 = 1.0f / li1;
    #pragma unroll
    for (int nt = 0; nt < 8; nt++) {
        const long long o0 = (long long)(b * NT + r0) * (NC / 2) + h * (NHD / 2) + nt * 4 + tig;
        const long long o1 = (long long)(b * NT + r1) * (NC / 2) + h * (NHD / 2) + nt * 4 + tig;
        float a0 = oC[nt][0] * inv0, a1 = oC[nt][1] * inv0;
        float a2 = oC[nt][2] * inv1, a3 = oC[nt][3] * inv1;
        uint32_t h0 = pack_bf2(a0, a1);
        uint32_t h1 = pack_bf2(a2, a3);
        yhi[o0] = h0; ylo[o0] = lo_pair(h0, a0, a1);
        yhi[o1] = h1; ylo[o1] = lo_pair(h1, a2, a3);
    }
}

// ---------------- loss (one-pass online softmax) ----------------
__global__ void k_loss_rows(const float* __restrict__ logits,
                            const int* __restrict__ targets,
                            float* loss_sum, float* loss_cnt)
{
    int row = blockIdx.x;
    int tid = threadIdx.x;
    const float* lr = logits + (long long)row * NV;
    __shared__ float rm[256];
    __shared__ float rs[256];

    float m = -1e30f, ssum = 0.f;
    for (int i = tid; i < NV; i += 256) {
        float xv = lr[i];
        if (xv > m) { ssum = ssum * __expf(m - xv) + 1.f; m = xv; }
        else        { ssum += __expf(xv - m); }
    }
    rm[tid] = m; rs[tid] = ssum; __syncthreads();
    for (int o = 128; o > 0; o >>= 1) {
        if (tid < o) {
            float m2 = rm[tid + o], s2 = rs[tid + o];
            float mn = fmaxf(rm[tid], m2);
            rs[tid] = rs[tid] * __expf(rm[tid] - mn) + s2 * __expf(m2 - mn);
            rm[tid] = mn;
        }
        __syncthreads();
    }

    if (tid == 0) {
        int t = targets[row];
        if (t != -1) {
            int tc = t < 0 ? 0 : (t > NV - 1 ? NV - 1 : t);
            float nll = (rm[0] + logf(rs[0])) - lr[tc];
            atomicAdd(loss_sum, nll);
            atomicAdd(loss_cnt, 1.0f);
        }
    }
}

__global__ void k_loss_fin(float* dst, const float* s, const float* c)
{
    if (dst) *dst = *s / fmaxf(*c, 1.0f);
}

// ---------------- host orchestration ----------------
extern "C" void kernel_launch(void* const* d_in, const int* in_sizes, int n_in,
                              void* d_out, int out_size)
{
    const int*   idx      = (const int*)  d_in[0];
    const int*   targets  = (const int*)  d_in[1];
    const float* wte      = (const float*)d_in[2];
    const float* wpe      = (const float*)d_in[3];
    const float* ln1_w    = (const float*)d_in[4];
    const float* ln1_b    = (const float*)d_in[5];
    const float* qkv_w    = (const float*)d_in[6];
    const float* qkv_b    = (const float*)d_in[7];
    const float* proj_w   = (const float*)d_in[8];
    const float* proj_b   = (const float*)d_in[9];
    const float* ln2_w    = (const float*)d_in[10];
    const float* ln2_b    = (const float*)d_in[11];
    const float* fc_w     = (const float*)d_in[12];
    const float* fc_b     = (const float*)d_in[13];
    const float* fc2_w    = (const float*)d_in[14];
    const float* fc2_b    = (const float*)d_in[15];
    const float* lnf_w    = (const float*)d_in[16];
    const float* lnf_b    = (const float*)d_in[17];
    const float* head_w   = (const float*)d_in[18];

    float *x, *qkv, *lscratch, *lsum, *lcnt;
    uint32_t *hhi, *hlo, *ahi, *alo, *fhi, *flo, *whi, *wlo;
    uint32_t *qphi, *qplo, *kphi, *kplo, *vthi, *vtlo;
    cudaGetSymbolAddress((void**)&x,    g_x);
    cudaGetSymbolAddress((void**)&qkv,  g_qkv);
    cudaGetSymbolAddress((void**)&hhi,  g_h_hi);
    cudaGetSymbolAddress((void**)&hlo,  g_h_lo);
    cudaGetSymbolAddress((void**)&ahi,  g_att_hi);
    cudaGetSymbolAddress((void**)&alo,  g_att_lo);
    cudaGetSymbolAddress((void**)&fhi,  g_fch_hi);
    cudaGetSymbolAddress((void**)&flo,  g_fch_lo);
    cudaGetSymbolAddress((void**)&whi,  g_whi);
    cudaGetSymbolAddress((void**)&wlo,  g_wlo);
    cudaGetSymbolAddress((void**)&qphi, g_qphi);
    cudaGetSymbolAddress((void**)&qplo, g_qplo);
    cudaGetSymbolAddress((void**)&kphi, g_kphi);
    cudaGetSymbolAddress((void**)&kplo, g_kplo);
    cudaGetSymbolAddress((void**)&vthi, g_vthi);
    cudaGetSymbolAddress((void**)&vtlo, g_vtlo);
    cudaGetSymbolAddress((void**)&lscratch, g_logits_scratch);
    cudaGetSymbolAddress((void**)&lsum, g_loss_sum);
    cudaGetSymbolAddress((void**)&lcnt, g_loss_cnt);

    cudaFuncSetAttribute(k_gemm_bf,    cudaFuncAttributeMaxDynamicSharedMemorySize, GEMM_SMEM);
    cudaFuncSetAttribute(k_gemm_bf512, cudaFuncAttributeMaxDynamicSharedMemorySize, GEMM5_SMEM);
    cudaFuncSetAttribute(k_attn_mma,   cudaFuncAttributeMaxDynamicSharedMemorySize, ATT_SMEM);

    float* logits = (out_size >= NBTV) ? (float*)d_out : lscratch;
    float* loss_dst = nullptr;
    if (out_size >= NBTV + 1)      loss_dst = (float*)d_out + NBTV;
    else if (out_size < NBTV)      loss_dst = (float*)d_out;

    dim3 attn_grid(NT / 64, NH, NB);
    dim3 split_grid(NT / 64, NH, NB);

    // launch order: ncu captures launch #4 -> QKV GEMM (l=0, bf512)
    {
        dim3 blk(32, 8);
        k_wsplit_all<<<WS_TOTAL_BLOCKS, blk>>>(qkv_w, proj_w, fc_w, fc2_w, head_w, whi, wlo);  // 1
    }
    {
        int n = NBT * NC;
        k_embed<<<(n + 255) / 256, 256>>>(idx, wte, wpe, x);   // 2
    }
    k_layernorm_p<<<NBT / 4, 128>>>(x, ln1_w, ln1_b, hhi, hlo);  // 3
    {
        dim3 grid(NBT / 256, (3 * NC + 127) / 128);
        k_gemm_bf512<<<grid, 512, GEMM5_SMEM>>>(hhi, hlo,        // 4 <- profiled
            whi + OFF_QKV, wlo + OFF_QKV,
            qkv_b, nullptr, qkv, nullptr, nullptr,
            NBT, 3 * NC, NC / 2, 0);
    }
    k_zero_loss<<<1, 1>>>(lsum, lcnt);                           // 5

    for (int l = 0; l < NL; l++) {
        if (l > 0) {
            k_layernorm_p<<<NBT / 4, 128>>>(x, ln1_w + l * NC, ln1_b + l * NC, hhi, hlo);
            dim3 grid(NBT / 256, (3 * NC + 127) / 128);
            k_gemm_bf512<<<grid, 512, GEMM5_SMEM>>>(hhi, hlo,
                whi + OFF_QKV + l * SZ_QKV, wlo + OFF_QKV + l * SZ_QKV,
                qkv_b + l * 3 * NC, nullptr, qkv, nullptr, nullptr,
                NBT, 3 * NC, NC / 2, 0);
        }
        k_qkvsplit<<<split_grid, 128>>>(qkv, qphi, qplo, kphi, kplo, vthi, vtlo);
        k_attn_mma<<<attn_grid, 128, ATT_SMEM>>>(qphi, qplo, kphi, kplo, vthi, vtlo, ahi, alo);
        {
            dim3 grid(NBT / 128, (NC + 127) / 128);
            k_gemm_bf<<<grid, 256, GEMM_SMEM>>>(ahi, alo,
                whi + OFF_PROJ + l * SZ_PROJ, wlo + OFF_PROJ + l * SZ_PROJ,
                proj_b + l * NC, x, x, nullptr, nullptr,
                NBT, NC, NC / 2, 0);
        }
        k_layernorm_p<<<NBT / 4, 128>>>(x, ln2_w + l * NC, ln2_b + l * NC, hhi, hlo);
        {
            dim3 grid(NBT / 256, (4 * NC + 127) / 128);
            k_gemm_bf512<<<grid, 512, GEMM5_SMEM>>>(hhi, hlo,
                whi + OFF_FC + l * SZ_FC, wlo + OFF_FC + l * SZ_FC,
                fc_b + l * 4 * NC, nullptr, nullptr, fhi, flo,
                NBT, 4 * NC, NC / 2, 1);
        }
        {
            dim3 grid(NBT / 128, (NC + 127) / 128);
            k_gemm_bf<<<grid, 256, GEMM_SMEM>>>(fhi, flo,
                whi + OFF_FC2 + l * SZ_FC2, wlo + OFF_FC2 + l * SZ_FC2,
                fc2_b + l * NC, x, x, nullptr, nullptr,
                NBT, NC, 4 * NC / 2, 0);
        }
    }

    k_layernorm_p<<<NBT / 4, 128>>>(x, lnf_w, lnf_b, hhi, hlo);

    {
        dim3 grid(NBT / 256, (NV + 127) / 128);
        k_gemm_bf512<<<grid, 512, GEMM5_SMEM>>>(hhi, hlo,
            whi + OFF_HEAD, wlo + OFF_HEAD,
            nullptr, nullptr, logits, nullptr, nullptr,
            NBT, NV, NC / 2, 0);
    }

    k_loss_rows<<<NBT, 256>>>(logits, targets, lsum, lcnt);
    k_loss_fin<<<1, 1>>>(loss_dst, lsum, lcnt);
}

// round 16
// speedup vs baseline: 1.1412x; 1.0668x over previous
#include <cuda_runtime.h>
#include <math.h>
#include <stdint.h>

// ---------------- problem constants ----------------
#define NB   4
#define NT   1024
#define NC   768
#define NH   12
#define NHD  64
#define NL   12
#define NV   50257
#define NBT  (NB*NT)     // 4096
#define NBTV (NBT*NV)

// weight plane offsets (uint32 units, transposed [N][K/2] per matrix)
#define OFF_QKV  0LL
#define SZ_QKV   (2304LL*384)
#define OFF_PROJ (OFF_QKV + 12*SZ_QKV)
#define SZ_PROJ  (768LL*384)
#define OFF_FC   (OFF_PROJ + 12*SZ_PROJ)
#define SZ_FC    (3072LL*384)
#define OFF_FC2  (OFF_FC + 12*SZ_FC)
#define SZ_FC2   (768LL*1536)
#define OFF_HEAD (OFF_FC2 + 12*SZ_FC2)
#define SZ_HEAD  (50257LL*384)
#define W_TOTAL  (OFF_HEAD + SZ_HEAD)

// ---------------- scratch ----------------
__device__ float    g_x   [NBT*NC];
__device__ float    g_qkv [NBT*3*NC];
__device__ uint32_t g_h_hi [NBT*NC/2];
__device__ uint32_t g_h_lo [NBT*NC/2];
__device__ uint32_t g_att_hi[NBT*NC/2];
__device__ uint32_t g_att_lo[NBT*NC/2];
__device__ uint32_t g_fch_hi[NBT*4*NC/2];
__device__ uint32_t g_fch_lo[NBT*4*NC/2];
__device__ uint32_t g_whi[W_TOTAL];
__device__ uint32_t g_wlo[W_TOTAL];
// packed attention operand planes: Q/K rows [bh][t][32w], Vt [bh][d][512w]
#define QK_WORDS (NB*NH*NT*32)
__device__ uint32_t g_qphi[QK_WORDS];
__device__ uint32_t g_qplo[QK_WORDS];
__device__ uint32_t g_kphi[QK_WORDS];
__device__ uint32_t g_kplo[QK_WORDS];
__device__ uint32_t g_vthi[QK_WORDS];
__device__ uint32_t g_vtlo[QK_WORDS];
__device__ float    g_logits_scratch[NBTV];
__device__ float    g_loss_sum;
__device__ float    g_loss_cnt;

__device__ __forceinline__ float gelu_f(float u) {
    return 0.5f * u * (1.0f + tanhf(0.7978845608028654f * (u + 0.044715f * u * u * u)));
}

__device__ __forceinline__ uint32_t pack_bf2(float even, float odd) {
    uint32_t r;
    asm("cvt.rn.bf16x2.f32 %0, %1, %2;" : "=r"(r) : "f"(odd), "f"(even));
    return r;
}
__device__ __forceinline__ uint32_t lo_pair(uint32_t hp, float even, float odd) {
    float e_h = __uint_as_float(hp << 16);
    float o_h = __uint_as_float(hp & 0xffff0000u);
    return pack_bf2(even - e_h, odd - o_h);
}

__device__ __forceinline__ void mma_bf16(float* c, const uint32_t* a, const uint32_t* b) {
    asm volatile(
        "mma.sync.aligned.m16n8k16.row.col.f32.bf16.bf16.f32 "
        "{%0,%1,%2,%3}, {%4,%5,%6,%7}, {%8,%9}, {%0,%1,%2,%3};"
        : "+f"(c[0]), "+f"(c[1]), "+f"(c[2]), "+f"(c[3])
        : "r"(a[0]), "r"(a[1]), "r"(a[2]), "r"(a[3]), "r"(b[0]), "r"(b[1]));
}

__device__ __forceinline__ uint32_t smem_u32(const void* p) {
    uint32_t a;
    asm("{ .reg .u64 t; cvta.to.shared.u64 t, %1; cvt.u32.u64 %0, t; }" : "=r"(a) : "l"(p));
    return a;
}
__device__ __forceinline__ void cpa16(uint32_t saddr, const void* g, uint32_t srcsz) {
    asm volatile("cp.async.cg.shared.global [%0], [%1], 16, %2;"
                 :: "r"(saddr), "l"(g), "r"(srcsz) : "memory");
}
#define CPA_COMMIT() asm volatile("cp.async.commit_group;" ::: "memory")
#define CPA_WAIT4()  asm volatile("cp.async.wait_group 4;" ::: "memory")
#define CPA_WAIT1()  asm volatile("cp.async.wait_group 1;" ::: "memory")
#define CPA_WAIT0()  asm volatile("cp.async.wait_group 0;" ::: "memory")

__device__ __forceinline__ void ldsm4(uint32_t* r, uint32_t addr) {
    asm volatile("ldmatrix.sync.aligned.m8n8.x4.shared.b16 {%0,%1,%2,%3}, [%4];"
                 : "=r"(r[0]), "=r"(r[1]), "=r"(r[2]), "=r"(r[3]) : "r"(addr));
}

// ---------------- small kernels ----------------
__global__ void k_embed(const int* __restrict__ idx,
                        const float* __restrict__ wte,
                        const float* __restrict__ wpe,
                        float* __restrict__ x,
                        float* loss_sum, float* loss_cnt)
{
    int i = blockIdx.x * blockDim.x + threadIdx.x;
    if (i == 0) { *loss_sum = 0.f; *loss_cnt = 0.f; }
    if (i >= NBT * NC) return;
    int c  = i % NC;
    int bt = i / NC;
    int t  = bt % NT;
    x[i] = wte[(long long)idx[bt] * NC + c] + wpe[t * NC + c];
}

// ---- single-launch weight transpose+split over all 49 matrices ----
#define WS_TOTAL_BLOCKS 60324
__global__ void k_wsplit_all(const float* __restrict__ qkv_w,
                             const float* __restrict__ proj_w,
                             const float* __restrict__ fc_w,
                             const float* __restrict__ fc2_w,
                             const float* __restrict__ head_w,
                             uint32_t* __restrict__ Whi,
                             uint32_t* __restrict__ Wlo)
{
    __shared__ uint32_t shi[32][33];
    __shared__ uint32_t slo[32][33];

    int bid = blockIdx.x;
    const float* W;
    long long dst;
    int K, N, ntn, t;
    if (bid < 10368) {
        int m = bid / 864; t = bid % 864;
        W = qkv_w + (long long)m * 768 * 2304; dst = OFF_QKV + m * SZ_QKV;
        K = 768; N = 2304; ntn = 72;
    } else if (bid < 13824) {
        bid -= 10368; int m = bid / 288; t = bid % 288;
        W = proj_w + (long long)m * 768 * 768; dst = OFF_PROJ + m * SZ_PROJ;
        K = 768; N = 768; ntn = 24;
    } else if (bid < 27648) {
        bid -= 13824; int m = bid / 1152; t = bid % 1152;
        W = fc_w + (long long)m * 768 * 3072; dst = OFF_FC + m * SZ_FC;
        K = 768; N = 3072; ntn = 96;
    } else if (bid < 41472) {
        bid -= 27648; int m = bid / 1152; t = bid % 1152;
        W = fc2_w + (long long)m * 3072 * 768; dst = OFF_FC2 + m * SZ_FC2;
        K = 3072; N = 768; ntn = 24;
    } else {
        t = bid - 41472;
        W = head_w; dst = OFF_HEAD;
        K = 768; N = NV; ntn = 1571;
    }
    const int K2 = K >> 1;
    const int n0  = (t % ntn) * 32;
    const int kp0 = (t / ntn) * 32;
    const int tx = threadIdx.x;
    const int ty = threadIdx.y;

    #pragma unroll
    for (int r = ty; r < 32; r += 8) {
        int kp = kp0 + r;
        int n  = n0 + tx;
        if (kp < K2 && n < N) {
            float w0 = W[(long long)(2 * kp) * N + n];
            float w1 = W[(long long)(2 * kp + 1) * N + n];
            uint32_t hp = pack_bf2(w0, w1);
            shi[r][tx] = hp;
            slo[r][tx] = lo_pair(hp, w0, w1);
        }
    }
    __syncthreads();
    #pragma unroll
    for (int r = ty; r < 32; r += 8) {
        int n  = n0 + r;
        int kp = kp0 + tx;
        if (kp < K2 && n < N) {
            long long o = dst + (long long)n * K2 + kp;
            Whi[o] = shi[tx][r];
            Wlo[o] = slo[tx][r];
        }
    }
}

// ---- warp-per-row layernorm -> packed planes ----
__global__ __launch_bounds__(128)
void k_layernorm_p(const float* __restrict__ x,
                   const float* __restrict__ w,
                   const float* __restrict__ b,
                   uint32_t* __restrict__ hhi,
                   uint32_t* __restrict__ hlo)
{
    const int lane = threadIdx.x & 31;
    const int row = blockIdx.x * 4 + (threadIdx.x >> 5);
    const float* xr = x + (long long)row * NC;

    float4 v[6];
    #pragma unroll
    for (int j = 0; j < 6; j++)
        v[j] = *(const float4*)(xr + (j * 32 + lane) * 4);

    float s = 0.f;
    #pragma unroll
    for (int j = 0; j < 6; j++) s += v[j].x + v[j].y + v[j].z + v[j].w;
    #pragma unroll
    for (int off = 16; off > 0; off >>= 1) s += __shfl_xor_sync(0xffffffffu, s, off);
    const float mu = s * (1.0f / NC);

    float var = 0.f;
    #pragma unroll
    for (int j = 0; j < 6; j++) {
        float a0 = v[j].x - mu, a1 = v[j].y - mu, a2 = v[j].z - mu, a3 = v[j].w - mu;
        var += a0 * a0 + a1 * a1 + a2 * a2 + a3 * a3;
    }
    #pragma unroll
    for (int off = 16; off > 0; off >>= 1) var += __shfl_xor_sync(0xffffffffu, var, off);
    const float rstd = rsqrtf(var * (1.0f / NC) + 1e-5f);

    const long long base = (long long)row * (NC / 2);
    #pragma unroll
    for (int j = 0; j < 6; j++) {
        const int c = (j * 32 + lane) * 4;
        float n0 = (v[j].x - mu) * rstd * w[c]     + b[c];
        float n1 = (v[j].y - mu) * rstd * w[c + 1] + b[c + 1];
        float n2 = (v[j].z - mu) * rstd * w[c + 2] + b[c + 2];
        float n3 = (v[j].w - mu) * rstd * w[c + 3] + b[c + 3];
        uint2 hp, lp;
        hp.x = pack_bf2(n0, n1); lp.x = lo_pair(hp.x, n0, n1);
        hp.y = pack_bf2(n2, n3); lp.y = lo_pair(hp.y, n2, n3);
        *(uint2*)(hhi + base + (c >> 1)) = hp;
        *(uint2*)(hlo + base + (c >> 1)) = lp;
    }
}

// ---- per-layer QKV -> packed attention planes (convert once) ----
__global__ __launch_bounds__(128)
void k_qkvsplit(const float* __restrict__ qkv,
                uint32_t* __restrict__ qhi, uint32_t* __restrict__ qlo,
                uint32_t* __restrict__ khi, uint32_t* __restrict__ klo,
                uint32_t* __restrict__ vthi, uint32_t* __restrict__ vtlo)
{
    __shared__ float stage[64][68];
    const int t0 = blockIdx.x * 64;
    const int h  = blockIdx.y;
    const int b  = blockIdx.z;
    const int tid = threadIdx.x;
    const int r = tid >> 1;
    const int hc = tid & 1;
    const long long bh = (long long)(b * NH + h);
    const float* base = qkv + (long long)b * NT * 3 * NC;

    {
        const float* qrow = base + (long long)(t0 + r) * (3 * NC) + h * NHD + hc * 32;
        const float* krow = qrow + NC;
        const long long out = (bh * NT + t0 + r) * 32 + hc * 16;
        #pragma unroll
        for (int c4 = 0; c4 < 4; c4++) {
            uint4 qh, ql, kh, kl;
            uint32_t* qhp = &qh.x; uint32_t* qlp = &ql.x;
            uint32_t* khp = &kh.x; uint32_t* klp = &kl.x;
            #pragma unroll
            for (int e = 0; e < 4; e++) {
                const int wd = c4 * 4 + e;
                float qe = qrow[2 * wd], qo = qrow[2 * wd + 1];
                qhp[e] = pack_bf2(qe, qo); qlp[e] = lo_pair(qhp[e], qe, qo);
                float ke = krow[2 * wd], ko = krow[2 * wd + 1];
                khp[e] = pack_bf2(ke, ko); klp[e] = lo_pair(khp[e], ke, ko);
            }
            *(uint4*)(qhi + out + c4 * 4) = qh;
            *(uint4*)(qlo + out + c4 * 4) = ql;
            *(uint4*)(khi + out + c4 * 4) = kh;
            *(uint4*)(klo + out + c4 * 4) = kl;
        }
    }

    {
        const float* vrow = base + (long long)(t0 + r) * (3 * NC) + 2 * NC + h * NHD + hc * 32;
        #pragma unroll
        for (int j = 0; j < 8; j++)
            *(float4*)(&stage[r][hc * 32 + j * 4]) = *(const float4*)(vrow + j * 4);
    }
    __syncthreads();

    {
        const int d = r;
        const long long out = (bh * NHD + d) * (NT / 2) + t0 / 2 + hc * 16;
        #pragma unroll
        for (int c4 = 0; c4 < 4; c4++) {
            uint4 vh, vl;
            uint32_t* vhp = &vh.x; uint32_t* vlp = &vl.x;
            #pragma unroll
            for (int e = 0; e < 4; e++) {
                const int tok = hc * 32 + (c4 * 4 + e) * 2;
                float ve = stage[tok][d], vo = stage[tok + 1][d];
                vhp[e] = pack_bf2(ve, vo); vlp[e] = lo_pair(vhp[e], ve, vo);
            }
            *(uint4*)(vthi + out + c4 * 4) = vh;
            *(uint4*)(vtlo + out + c4 * 4) = vl;
        }
    }
}

// ---------------- split-bf16 GEMM, 128x128 tile (all GEMMs) ---------------
#define GEMM_SMEM 98304

__global__ __launch_bounds__(256, 2)
void k_gemm_bf(const uint32_t* __restrict__ Ahi, const uint32_t* __restrict__ Alo,
               const uint32_t* __restrict__ Bhi, const uint32_t* __restrict__ Blo,
               const float* __restrict__ bias, const float* __restrict__ res,
               float* __restrict__ Cf,
               uint32_t* __restrict__ Chi, uint32_t* __restrict__ Clo,
               int M, int N, int K2, int act)
{
    extern __shared__ uint32_t smw[];
    const uint32_t sbase = smem_u32(smw);

    const int tid  = threadIdx.x;
    const int lane = tid & 31;
    const int w    = tid >> 5;
    const int bm   = blockIdx.x * 128;
    const int bn   = blockIdx.y * 128;
    const int wm   = (w & 1) * 64;
    const int wn   = (w >> 1) * 32;
    const int g    = lane >> 2;
    const int tig  = lane & 3;

    const int m    = tid >> 1;
    const int half = tid & 1;
    const uint32_t swoff = (uint32_t)((half ^ ((m >> 2) & 1)) << 4);
    const long long aoff = (long long)(bm + m) * K2 + half * 4;
    const int bn_row = (bn + m < N) ? (bn + m) : (N - 1);
    const long long boff = (long long)bn_row * K2 + half * 4;
    const uint32_t bsz = (bn + m < N) ? 16u : 0u;

    const int l15 = lane & 15;
    const uint32_t a_sw = (uint32_t)((((lane >> 4) << 2) ^ (((l15 >> 2) & 1) << 2)) << 2);
    const uint32_t a_base = sbase + (uint32_t)(wm + l15) * 32 + a_sw;
    const int l8 = lane & 7;
    const uint32_t b_sw = (uint32_t)(((((lane >> 3) & 1) << 2) ^ (((l8 >> 2) & 1) << 2)) << 2);
    const uint32_t b_base = sbase + 8192u +
        (uint32_t)(wn + ((lane >> 4) & 1) * 8 + l8) * 32 + b_sw;

    float acc[16][4];
    #pragma unroll
    for (int i = 0; i < 16; i++)
        #pragma unroll
        for (int j = 0; j < 4; j++) acc[i][j] = 0.f;

#define ISSUE_STAGE(S_) do {                                              \
        const int _buf = (S_) % 6;                                        \
        const uint32_t _so = sbase + _buf * 16384 + m * 32 + swoff;       \
        const long long _ko = (long long)(S_) * 8;                        \
        cpa16(_so,         Ahi + aoff + _ko, 16u);                        \
        cpa16(_so + 4096,  Alo + aoff + _ko, 16u);                        \
        cpa16(_so + 8192,  Bhi + boff + _ko, bsz);                        \
        cpa16(_so + 12288, Blo + boff + _ko, bsz);                        \
        CPA_COMMIT();                                                     \
    } while (0)

    const int S = K2 >> 3;
    ISSUE_STAGE(0);
    ISSUE_STAGE(1);
    ISSUE_STAGE(2);
    ISSUE_STAGE(3);
    ISSUE_STAGE(4);

    for (int s = 0; s < S; s++) {
        CPA_WAIT4();
        __syncthreads();
        if (s + 5 < S) { ISSUE_STAGE(s + 5); } else { CPA_COMMIT(); }

        const uint32_t stoff = (uint32_t)((s % 6) * 16384);

        uint32_t bh[8], bl[8];
        ldsm4(bh,     b_base + stoff);
        ldsm4(bh + 4, b_base + stoff + 512);
        ldsm4(bl,     b_base + stoff + 4096);
        ldsm4(bl + 4, b_base + stoff + 4096 + 512);

        #pragma unroll
        for (int mt = 0; mt < 4; mt++) {
            uint32_t ah[4], al[4];
            ldsm4(ah, a_base + stoff + mt * 512);
            ldsm4(al, a_base + stoff + mt * 512 + 4096);
            #pragma unroll
            for (int nt = 0; nt < 4; nt++) {
                mma_bf16(acc[mt * 4 + nt], ah, bh + nt * 2);
                mma_bf16(acc[mt * 4 + nt], ah, bl + nt * 2);
                mma_bf16(acc[mt * 4 + nt], al, bh + nt * 2);
            }
        }
    }
#undef ISSUE_STAGE

    const bool evenN = ((N & 1) == 0);
    #pragma unroll
    for (int mt = 0; mt < 4; mt++) {
        #pragma unroll
        for (int nt = 0; nt < 4; nt++) {
            const float* c = acc[mt * 4 + nt];
            const int n = bn + wn + nt * 8 + tig * 2;
            #pragma unroll
            for (int hf = 0; hf < 2; hf++) {
                const int mm = bm + wm + mt * 16 + g + hf * 8;
                float v0 = c[hf * 2 + 0];
                float v1 = c[hf * 2 + 1];
                if (act == 1) {
                    if (bias) { v0 += bias[n]; v1 += bias[n + 1]; }
                    v0 = gelu_f(v0); v1 = gelu_f(v1);
                    uint32_t hp = pack_bf2(v0, v1);
                    long long o = (long long)mm * (N >> 1) + (n >> 1);
                    Chi[o] = hp;
                    Clo[o] = lo_pair(hp, v0, v1);
                } else {
                    const long long rowoff = (long long)mm * N;
                    if (n + 1 < N) {
                        if (bias) { v0 += bias[n]; v1 += bias[n + 1]; }
                        if (res)  { v0 += res[rowoff + n]; v1 += res[rowoff + n + 1]; }
                        if (evenN) {
                            *(float2*)(Cf + rowoff + n) = make_float2(v0, v1);
                        } else {
                            Cf[rowoff + n]     = v0;
                            Cf[rowoff + n + 1] = v1;
                        }
                    } else if (n < N) {
                        if (bias) v0 += bias[n];
                        if (res)  v0 += res[rowoff + n];
                        Cf[rowoff + n] = v0;
                    }
                }
            }
        }
    }
}

// ---------------- tensor-core flash attention (precomputed planes) --------
#define ATT_SMEM 81920

__global__ __launch_bounds__(128)
void k_attn_mma(const uint32_t* __restrict__ qphi, const uint32_t* __restrict__ qplo,
                const uint32_t* __restrict__ kphi, const uint32_t* __restrict__ kplo,
                const uint32_t* __restrict__ vthi, const uint32_t* __restrict__ vtlo,
                uint32_t* __restrict__ yhi, uint32_t* __restrict__ ylo)
{
    extern __shared__ char smatt[];
    const uint32_t sb = smem_u32(smatt);

    const int tid  = threadIdx.x;
    const int lane = tid & 31;
    const int w    = tid >> 5;
    const int g    = lane >> 2;
    const int tig  = lane & 3;
    const int q0   = blockIdx.x * 64;
    const int h    = blockIdx.y;
    const int b    = blockIdx.z;
    const long long bh = (long long)(b * NH + h);

    const int r  = tid >> 1;
    const int cb = (tid & 1) * 4;
    const uint32_t rsw = (uint32_t)(r & 7);

    {
        const long long grow = (bh * NT + q0 + r) * 32;
        const uint32_t so = sb + (uint32_t)(r * 128);
        #pragma unroll
        for (int cc = 0; cc < 4; cc++) {
            const int c = cb + cc;
            const uint32_t sw = (uint32_t)((c ^ rsw) << 4);
            cpa16(so + sw,        qphi + grow + c * 4, 16u);
            cpa16(so + 8192 + sw, qplo + grow + c * 4, 16u);
        }
        CPA_COMMIT();
    }

#define ISSUE_KV(J_) do {                                                   \
        const uint32_t _bo = sb + 16384u + (uint32_t)(((J_) & 1) * 32768);  \
        const long long _kg = (bh * NT + (long long)(J_) * 64 + r) * 32;    \
        const long long _vg = (bh * NHD + r) * (NT / 2) + (long long)(J_) * 32; \
        const uint32_t _so = _bo + (uint32_t)(r * 128);                     \
        _Pragma("unroll")                                                   \
        for (int cc = 0; cc < 4; cc++) {                                    \
            const int c = cb + cc;                                          \
            const uint32_t sw = (uint32_t)((c ^ rsw) << 4);                 \
            cpa16(_so + sw,         kphi + _kg + c * 4, 16u);               \
            cpa16(_so + 8192 + sw,  kplo + _kg + c * 4, 16u);               \
            cpa16(_so + 16384 + sw, vthi + _vg + c * 4, 16u);               \
            cpa16(_so + 24576 + sw, vtlo + _vg + c * 4, 16u);               \
        }                                                                   \
        CPA_COMMIT();                                                       \
    } while (0)

    const int ntiles = blockIdx.x + 1;
    ISSUE_KV(0);

    float oC[8][4];
    #pragma unroll
    for (int i = 0; i < 8; i++)
        #pragma unroll
        for (int j = 0; j < 4; j++) oC[i][j] = 0.f;
    float mi0 = -1e30f, mi1 = -1e30f, li0 = 0.f, li1 = 0.f;

    const int qw = w * 16;
    const int r0 = q0 + qw + g;
    const int r1 = r0 + 8;

    for (int tj = 0; tj < ntiles; tj++) {
        const int j0 = tj * 64;
        if (tj + 1 < ntiles) { ISSUE_KV(tj + 1); CPA_WAIT1(); }
        else                 { CPA_WAIT0(); }
        __syncthreads();

        const uint32_t kb = sb + 16384u + (uint32_t)((tj & 1) * 32768);

        float sC[8][4];
        #pragma unroll
        for (int i = 0; i < 8; i++)
            #pragma unroll
            for (int j = 0; j < 4; j++) sC[i][j] = 0.f;

        #pragma unroll
        for (int ks = 0; ks < 4; ks++) {
            const int ar = qw + (lane & 15);
            const uint32_t aaddr = sb + (uint32_t)(ar * 128 +
                (((2 * ks + (lane >> 4)) ^ (ar & 7)) << 4));
            uint32_t qa_h[4], qa_l[4];
            ldsm4(qa_h, aaddr);
            ldsm4(qa_l, aaddr + 8192);
            #pragma unroll
            for (int np = 0; np < 4; np++) {
                const int br = np * 16 + ((lane >> 4) & 1) * 8 + (lane & 7);
                const uint32_t baddr = kb + (uint32_t)(br * 128 +
                    (((2 * ks + ((lane >> 3) & 1)) ^ (br & 7)) << 4));
                uint32_t kb_h[4], kb_l[4];
                ldsm4(kb_h, baddr);
                ldsm4(kb_l, baddr + 8192);
                mma_bf16(sC[2*np],   qa_h, kb_h);
                mma_bf16(sC[2*np],   qa_h, kb_l);
                mma_bf16(sC[2*np],   qa_l, kb_h);
                mma_bf16(sC[2*np+1], qa_h, kb_h + 2);
                mma_bf16(sC[2*np+1], qa_h, kb_l + 2);
                mma_bf16(sC[2*np+1], qa_l, kb_h + 2);
            }
        }

        const bool diag = (tj + 1 == ntiles);
        #pragma unroll
        for (int nt = 0; nt < 8; nt++) {
            const int c0 = j0 + nt * 8 + tig * 2;
            if (diag) {
                sC[nt][0] = (c0     <= r0) ? sC[nt][0] * 0.125f : -1e30f;
                sC[nt][1] = (c0 + 1 <= r0) ? sC[nt][1] * 0.125f : -1e30f;
                sC[nt][2] = (c0     <= r1) ? sC[nt][2] * 0.125f : -1e30f;
                sC[nt][3] = (c0 + 1 <= r1) ? sC[nt][3] * 0.125f : -1e30f;
            } else {
                sC[nt][0] *= 0.125f; sC[nt][1] *= 0.125f;
                sC[nt][2] *= 0.125f; sC[nt][3] *= 0.125f;
            }
        }

        float m0 = -1e30f, m1 = -1e30f;
        #pragma unroll
        for (int nt = 0; nt < 8; nt++) {
            m0 = fmaxf(m0, fmaxf(sC[nt][0], sC[nt][1]));
            m1 = fmaxf(m1, fmaxf(sC[nt][2], sC[nt][3]));
        }
        m0 = fmaxf(m0, __shfl_xor_sync(0xffffffffu, m0, 1));
        m0 = fmaxf(m0, __shfl_xor_sync(0xffffffffu, m0, 2));
        m1 = fmaxf(m1, __shfl_xor_sync(0xffffffffu, m1, 1));
        m1 = fmaxf(m1, __shfl_xor_sync(0xffffffffu, m1, 2));
        const float mn0 = fmaxf(mi0, m0), mn1 = fmaxf(mi1, m1);
        const float corr0 = __expf(mi0 - mn0), corr1 = __expf(mi1 - mn1);

        float rs0 = 0.f, rs1 = 0.f;
        uint32_t pa_h[4][4], pa_l[4][4];
        #pragma unroll
        for (int nt = 0; nt < 8; nt++) {
            float p0 = __expf(sC[nt][0] - mn0);
            float p1 = __expf(sC[nt][1] - mn0);
            float p2 = __expf(sC[nt][2] - mn1);
            float p3 = __expf(sC[nt][3] - mn1);
            rs0 += p0 + p1; rs1 += p2 + p3;
            const int ks = nt >> 1;
            const int rb = (nt & 1) * 2;
            uint32_t u01 = pack_bf2(p0, p1);
            uint32_t u23 = pack_bf2(p2, p3);
            pa_h[ks][rb]     = u01; pa_l[ks][rb]     = lo_pair(u01, p0, p1);
            pa_h[ks][rb + 1] = u23; pa_l[ks][rb + 1] = lo_pair(u23, p2, p3);
        }
        rs0 += __shfl_xor_sync(0xffffffffu, rs0, 1);
        rs0 += __shfl_xor_sync(0xffffffffu, rs0, 2);
        rs1 += __shfl_xor_sync(0xffffffffu, rs1, 1);
        rs1 += __shfl_xor_sync(0xffffffffu, rs1, 2);
        li0 = li0 * corr0 + rs0; mi0 = mn0;
        li1 = li1 * corr1 + rs1; mi1 = mn1;
        #pragma unroll
        for (int nt = 0; nt < 8; nt++) {
            oC[nt][0] *= corr0; oC[nt][1] *= corr0;
            oC[nt][2] *= corr1; oC[nt][3] *= corr1;
        }

        #pragma unroll
        for (int ks = 0; ks < 4; ks++) {
            #pragma unroll
            for (int np = 0; np < 4; np++) {
                const int br = np * 16 + ((lane >> 4) & 1) * 8 + (lane & 7);
                const uint32_t baddr = kb + 16384u + (uint32_t)(br * 128 +
                    (((2 * ks + ((lane >> 3) & 1)) ^ (br & 7)) << 4));
                uint32_t vb_h[4], vb_l[4];
                ldsm4(vb_h, baddr);
                ldsm4(vb_l, baddr + 8192);
                mma_bf16(oC[2*np],   pa_h[ks], vb_h);
                mma_bf16(oC[2*np],   pa_h[ks], vb_l);
                mma_bf16(oC[2*np],   pa_l[ks], vb_h);
                mma_bf16(oC[2*np+1], pa_h[ks], vb_h + 2);
                mma_bf16(oC[2*np+1], pa_h[ks], vb_l + 2);
                mma_bf16(oC[2*np+1], pa_l[ks], vb_h + 2);
            }
        }
        __syncthreads();
    }
#undef ISSUE_KV

    const float inv0 = 1.0f / li0, inv1 = 1.0f / li1;
    #pragma unroll
    for (int nt = 0; nt < 8; nt++) {
        const long long o0 = (long long)(b * NT + r0) * (NC / 2) + h * (NHD / 2) + nt * 4 + tig;
        const long long o1 = (long long)(b * NT + r1) * (NC / 2) + h * (NHD / 2) + nt * 4 + tig;
        float a0 = oC[nt][0] * inv0, a1 = oC[nt][1] * inv0;
        float a2 = oC[nt][2] * inv1, a3 = oC[nt][3] * inv1;
        uint32_t h0 = pack_bf2(a0, a1);
        uint32_t h1 = pack_bf2(a2, a3);
        yhi[o0] = h0; ylo[o0] = lo_pair(h0, a0, a1);
        yhi[o1] = h1; ylo[o1] = lo_pair(h1, a2, a3);
    }
}

// ---------------- loss (one-pass online softmax, float4 body) -------------
__global__ void k_loss_rows(const float* __restrict__ logits,
                            const int* __restrict__ targets,
                            float* loss_sum, float* loss_cnt)
{
    int row = blockIdx.x;
    int tid = threadIdx.x;
    const float* lr = logits + (long long)row * NV;
    __shared__ float rm[256];
    __shared__ float rs[256];

    float m = -1e30f, ssum = 0.f;

    // alignment prologue: lr is 4B-aligned; lead scalars until 16B boundary
    const int lead = ((int)(16 - (((long long)row * NV * 4) & 15)) & 15) >> 2;
    for (int i = tid; i < lead; i += 256) {
        float xv = lr[i];
        if (xv > m) { ssum = ssum * __expf(m - xv) + 1.f; m = xv; }
        else        { ssum += __expf(xv - m); }
    }
    const int nvec = (NV - lead) >> 2;
    const float4* lv = (const float4*)(lr + lead);
    for (int i = tid; i < nvec; i += 256) {
        float4 v = lv[i];
        float xv;
        xv = v.x; if (xv > m) { ssum = ssum * __expf(m - xv) + 1.f; m = xv; } else ssum += __expf(xv - m);
        xv = v.y; if (xv > m) { ssum = ssum * __expf(m - xv) + 1.f; m = xv; } else ssum += __expf(xv - m);
        xv = v.z; if (xv > m) { ssum = ssum * __expf(m - xv) + 1.f; m = xv; } else ssum += __expf(xv - m);
        xv = v.w; if (xv > m) { ssum = ssum * __expf(m - xv) + 1.f; m = xv; } else ssum += __expf(xv - m);
    }
    for (int i = lead + nvec * 4 + tid; i < NV; i += 256) {
        float xv = lr[i];
        if (xv > m) { ssum = ssum * __expf(m - xv) + 1.f; m = xv; }
        else        { ssum += __expf(xv - m); }
    }

    rm[tid] = m; rs[tid] = ssum; __syncthreads();
    for (int o = 128; o > 0; o >>= 1) {
        if (tid < o) {
            float m2 = rm[tid + o], s2 = rs[tid + o];
            float mn = fmaxf(rm[tid], m2);
            rs[tid] = rs[tid] * __expf(rm[tid] - mn) + s2 * __expf(m2 - mn);
            rm[tid] = mn;
        }
        __syncthreads();
    }

    if (tid == 0) {
        int t = targets[row];
        if (t != -1) {
            int tc = t < 0 ? 0 : (t > NV - 1 ? NV - 1 : t);
            float nll = (rm[0] + logf(rs[0])) - lr[tc];
            atomicAdd(loss_sum, nll);
            atomicAdd(loss_cnt, 1.0f);
        }
    }
}

__global__ void k_loss_fin(float* dst, const float* s, const float* c)
{
    if (dst) *dst = *s / fmaxf(*c, 1.0f);
}

// ---------------- host orchestration ----------------
extern "C" void kernel_launch(void* const* d_in, const int* in_sizes, int n_in,
                              void* d_out, int out_size)
{
    const int*   idx      = (const int*)  d_in[0];
    const int*   targets  = (const int*)  d_in[1];
    const float* wte      = (const float*)d_in[2];
    const float* wpe      = (const float*)d_in[3];
    const float* ln1_w    = (const float*)d_in[4];
    const float* ln1_b    = (const float*)d_in[5];
    const float* qkv_w    = (const float*)d_in[6];
    const float* qkv_b    = (const float*)d_in[7];
    const float* proj_w   = (const float*)d_in[8];
    const float* proj_b   = (const float*)d_in[9];
    const float* ln2_w    = (const float*)d_in[10];
    const float* ln2_b    = (const float*)d_in[11];
    const float* fc_w     = (const float*)d_in[12];
    const float* fc_b     = (const float*)d_in[13];
    const float* fc2_w    = (const float*)d_in[14];
    const float* fc2_b    = (const float*)d_in[15];
    const float* lnf_w    = (const float*)d_in[16];
    const float* lnf_b    = (const float*)d_in[17];
    const float* head_w   = (const float*)d_in[18];

    float *x, *qkv, *lscratch, *lsum, *lcnt;
    uint32_t *hhi, *hlo, *ahi, *alo, *fhi, *flo, *whi, *wlo;
    uint32_t *qphi, *qplo, *kphi, *kplo, *vthi, *vtlo;
    cudaGetSymbolAddress((void**)&x,    g_x);
    cudaGetSymbolAddress((void**)&qkv,  g_qkv);
    cudaGetSymbolAddress((void**)&hhi,  g_h_hi);
    cudaGetSymbolAddress((void**)&hlo,  g_h_lo);
    cudaGetSymbolAddress((void**)&ahi,  g_att_hi);
    cudaGetSymbolAddress((void**)&alo,  g_att_lo);
    cudaGetSymbolAddress((void**)&fhi,  g_fch_hi);
    cudaGetSymbolAddress((void**)&flo,  g_fch_lo);
    cudaGetSymbolAddress((void**)&whi,  g_whi);
    cudaGetSymbolAddress((void**)&wlo,  g_wlo);
    cudaGetSymbolAddress((void**)&qphi, g_qphi);
    cudaGetSymbolAddress((void**)&qplo, g_qplo);
    cudaGetSymbolAddress((void**)&kphi, g_kphi);
    cudaGetSymbolAddress((void**)&kplo, g_kplo);
    cudaGetSymbolAddress((void**)&vthi, g_vthi);
    cudaGetSymbolAddress((void**)&vtlo, g_vtlo);
    cudaGetSymbolAddress((void**)&lscratch, g_logits_scratch);
    cudaGetSymbolAddress((void**)&lsum, g_loss_sum);
    cudaGetSymbolAddress((void**)&lcnt, g_loss_cnt);

    cudaFuncSetAttribute(k_gemm_bf,  cudaFuncAttributeMaxDynamicSharedMemorySize, GEMM_SMEM);
    cudaFuncSetAttribute(k_attn_mma, cudaFuncAttributeMaxDynamicSharedMemorySize, ATT_SMEM);

    float* logits = (out_size >= NBTV) ? (float*)d_out : lscratch;
    float* loss_dst = nullptr;
    if (out_size >= NBTV + 1)      loss_dst = (float*)d_out + NBTV;
    else if (out_size < NBTV)      loss_dst = (float*)d_out;

    dim3 attn_grid(NT / 64, NH, NB);
    dim3 split_grid(NT / 64, NH, NB);

    // launch order: ncu captures launch #4 -> QKV GEMM (l=0)
    {
        dim3 blk(32, 8);
        k_wsplit_all<<<WS_TOTAL_BLOCKS, blk>>>(qkv_w, proj_w, fc_w, fc2_w, head_w, whi, wlo);  // 1
    }
    {
        int n = NBT * NC;
        k_embed<<<(n + 255) / 256, 256>>>(idx, wte, wpe, x, lsum, lcnt);   // 2 (also zeroes loss)
    }
    k_layernorm_p<<<NBT / 4, 128>>>(x, ln1_w, ln1_b, hhi, hlo);  // 3
    {
        dim3 grid(NBT / 128, (3 * NC + 127) / 128);
        k_gemm_bf<<<grid, 256, GEMM_SMEM>>>(hhi, hlo,            // 4 <- profiled
            whi + OFF_QKV, wlo + OFF_QKV,
            qkv_b, nullptr, qkv, nullptr, nullptr,
            NBT, 3 * NC, NC / 2, 0);
    }

    for (int l = 0; l < NL; l++) {
        if (l > 0) {
            k_layernorm_p<<<NBT / 4, 128>>>(x, ln1_w + l * NC, ln1_b + l * NC, hhi, hlo);
            dim3 grid(NBT / 128, (3 * NC + 127) / 128);
            k_gemm_bf<<<grid, 256, GEMM_SMEM>>>(hhi, hlo,
                whi + OFF_QKV + l * SZ_QKV, wlo + OFF_QKV + l * SZ_QKV,
                qkv_b + l * 3 * NC, nullptr, qkv, nullptr, nullptr,
                NBT, 3 * NC, NC / 2, 0);
        }
        k_qkvsplit<<<split_grid, 128>>>(qkv, qphi, qplo, kphi, kplo, vthi, vtlo);
        k_attn_mma<<<attn_grid, 128, ATT_SMEM>>>(qphi, qplo, kphi, kplo, vthi, vtlo, ahi, alo);
        {
            dim3 grid(NBT / 128, (NC + 127) / 128);
            k_gemm_bf<<<grid, 256, GEMM_SMEM>>>(ahi, alo,
                whi + OFF_PROJ + l * SZ_PROJ, wlo + OFF_PROJ + l * SZ_PROJ,
                proj_b + l * NC, x, x, nullptr, nullptr,
                NBT, NC, NC / 2, 0);
        }
        k_layernorm_p<<<NBT / 4, 128>>>(x, ln2_w + l * NC, ln2_b + l * NC, hhi, hlo);
        {
            dim3 grid(NBT / 128, (4 * NC + 127) / 128);
            k_gemm_bf<<<grid, 256, GEMM_SMEM>>>(hhi, hlo,
                whi + OFF_FC + l * SZ_FC, wlo + OFF_FC + l * SZ_FC,
                fc_b + l * 4 * NC, nullptr, nullptr, fhi, flo,
                NBT, 4 * NC, NC / 2, 1);
        }
        {
            dim3 grid(NBT / 128, (NC + 127) / 128);
            k_gemm_bf<<<grid, 256, GEMM_SMEM>>>(fhi, flo,
                whi + OFF_FC2 + l * SZ_FC2, wlo + OFF_FC2 + l * SZ_FC2,
                fc2_b + l * NC, x, x, nullptr, nullptr,
                NBT, NC, 4 * NC / 2, 0);
        }
    }

    k_layernorm_p<<<NBT / 4, 128>>>(x, lnf_w, lnf_b, hhi, hlo);

    {
        dim3 grid(NBT / 128, (NV + 127) / 128);
        k_gemm_bf<<<grid, 256, GEMM_SMEM>>>(hhi, hlo,
            whi + OFF_HEAD, wlo + OFF_HEAD,
            nullptr, nullptr, logits, nullptr, nullptr,
            NBT, NV, NC / 2, 0);
    }

    k_loss_rows<<<NBT, 256>>>(logits, targets, lsum, lcnt);
    k_loss_fin<<<1, 1>>>(loss_dst, lsum, lcnt);
}